// round 1
// baseline (speedup 1.0000x reference)
#include <cuda_runtime.h>

// Problem constants
#define BB   2
#define SS   2048
#define DD   1024
#define HH   16
#define HDIM 64
#define MROWS (BB * SS)           // 4096
#define QKV_E (3 * DD)            // 3072
#define SCALE 0.125f              // 1/sqrt(64)

// Scratch (device globals per harness allocation rules)
__device__ __align__(16) float g_qkv[MROWS * QKV_E];   // [b*s][3072]
__device__ __align__(16) float g_o[MROWS * DD];        // [b*s][1024]

// ---------------------------------------------------------------------------
// NT SGEMM: C[M,N] = A[M,K] * B[N,K]^T (+ bias[n]); all row-major, K contiguous
// 128x128 block tile, BK=32, 256 threads, 8x8 per-thread microtile.
// ---------------------------------------------------------------------------
__global__ __launch_bounds__(256) void sgemm_nt(
    const float* __restrict__ A, const float* __restrict__ B,
    const float* __restrict__ bias, float* __restrict__ C,
    int M, int N, int K)
{
    __shared__ float As[32][132];   // [k][m], padded
    __shared__ float Bs[32][132];   // [k][n], padded

    const int tid = threadIdx.x;
    const int tm  = tid >> 4;       // 0..15
    const int tn  = tid & 15;       // 0..15
    const int m0  = blockIdx.y * 128;
    const int n0  = blockIdx.x * 128;

    const float* Ab = A + (size_t)m0 * K;
    const float* Bb = B + (size_t)n0 * K;

    float acc[8][8];
#pragma unroll
    for (int i = 0; i < 8; i++)
#pragma unroll
        for (int j = 0; j < 8; j++) acc[i][j] = 0.f;

    for (int k0 = 0; k0 < K; k0 += 32) {
#pragma unroll
        for (int v = 0; v < 4; v++) {
            int idx = v * 256 + tid;        // 0..1023
            int row = idx >> 3;             // 0..127
            int kq  = (idx & 7) << 2;       // 0,4,...,28
            float4 a = *(const float4*)(Ab + (size_t)row * K + k0 + kq);
            As[kq + 0][row] = a.x; As[kq + 1][row] = a.y;
            As[kq + 2][row] = a.z; As[kq + 3][row] = a.w;
            float4 b = *(const float4*)(Bb + (size_t)row * K + k0 + kq);
            Bs[kq + 0][row] = b.x; Bs[kq + 1][row] = b.y;
            Bs[kq + 2][row] = b.z; Bs[kq + 3][row] = b.w;
        }
        __syncthreads();

#pragma unroll
        for (int kk = 0; kk < 32; kk++) {
            float4 a0 = *(const float4*)&As[kk][tm * 8];
            float4 a1 = *(const float4*)&As[kk][tm * 8 + 4];
            float4 b0 = *(const float4*)&Bs[kk][tn * 8];
            float4 b1 = *(const float4*)&Bs[kk][tn * 8 + 4];
            float af[8] = {a0.x, a0.y, a0.z, a0.w, a1.x, a1.y, a1.z, a1.w};
            float bf[8] = {b0.x, b0.y, b0.z, b0.w, b1.x, b1.y, b1.z, b1.w};
#pragma unroll
            for (int i = 0; i < 8; i++)
#pragma unroll
                for (int j = 0; j < 8; j++)
                    acc[i][j] += af[i] * bf[j];
        }
        __syncthreads();
    }

#pragma unroll
    for (int i = 0; i < 8; i++) {
        int m = m0 + tm * 8 + i;
        float* Cr = C + (size_t)m * N + n0 + tn * 8;
#pragma unroll
        for (int j = 0; j < 8; j++) {
            float bv = bias ? bias[n0 + tn * 8 + j] : 0.f;
            Cr[j] = acc[i][j] + bv;
        }
    }
}

// ---------------------------------------------------------------------------
// Flash attention, fp32. One block per (b*h, 64-query tile). 128 threads.
// Thread microtile: 4 rows (tr = tid>>3, 16 values) x 8 cols (tc = tid&7).
// Qs/Ks stored [d][col] with XOR-8 swizzle for conflict-light transpose store
// and conflict-free float4 gemm reads. P round-trips through shared.
// ---------------------------------------------------------------------------
__global__ __launch_bounds__(128) void flash64(
    const float* __restrict__ qkv, float* __restrict__ og)
{
    __shared__ float Qs[64 * 64];   // [d][r], swizzled  (16 KB)
    __shared__ float KVs[64 * 64];  // K: [d][c] swizzled; V: [c][d] natural
    __shared__ float Ps[64 * 64];   // [c][r]

    const int tid = threadIdx.x;
    const int tr  = tid >> 3;       // 0..15 -> rows 4*tr..4*tr+3
    const int tc  = tid & 7;        // 0..7  -> cols 8*tc..8*tc+7
    const int q0  = blockIdx.x * 64;
    const int b   = blockIdx.y >> 4;
    const int h   = blockIdx.y & 15;

    const float* qp = qkv + (size_t)b * SS * QKV_E + DD     + h * HDIM;
    const float* kp = qkv + (size_t)b * SS * QKV_E + 2 * DD + h * HDIM;
    const float* vp = qkv + (size_t)b * SS * QKV_E          + h * HDIM;

    // Load Q tile transposed (Qs[d][r]) with swizzle
    for (int i = tid; i < 64 * 64; i += 128) {
        int r = i >> 6, d = i & 63;
        Qs[d * 64 + (r ^ ((d & 7) << 3))] = qp[(size_t)(q0 + r) * QKV_E + d];
    }

    float acc[4][8];
    float m_i[4], l_i[4];
#pragma unroll
    for (int i = 0; i < 4; i++) {
        m_i[i] = -1e30f; l_i[i] = 0.f;
#pragma unroll
        for (int j = 0; j < 8; j++) acc[i][j] = 0.f;
    }

    for (int kv0 = 0; kv0 < SS; kv0 += 64) {
        __syncthreads();   // prev iteration done with KVs (V) and Ps

        // Load K tile transposed (KVs[d][c]) with swizzle
        for (int i = tid; i < 64 * 64; i += 128) {
            int c = i >> 6, d = i & 63;
            KVs[d * 64 + (c ^ ((d & 7) << 3))] =
                kp[(size_t)(kv0 + c) * QKV_E + d];
        }
        __syncthreads();

        // S = Q K^T   (64x64x64)
        float s[4][8];
#pragma unroll
        for (int i = 0; i < 4; i++)
#pragma unroll
            for (int j = 0; j < 8; j++) s[i][j] = 0.f;

#pragma unroll 8
        for (int d = 0; d < 64; d++) {
            const int sw = (d & 7) << 3;
            float4 a  = *(const float4*)&Qs[d * 64 + ((tr * 4) ^ sw)];
            int    bo = d * 64 + ((tc * 8) ^ sw);
            float4 b0 = *(const float4*)&KVs[bo];
            float4 b1 = *(const float4*)&KVs[bo + 4];
            float af[4] = {a.x, a.y, a.z, a.w};
            float bf[8] = {b0.x, b0.y, b0.z, b0.w, b1.x, b1.y, b1.z, b1.w};
#pragma unroll
            for (int i = 0; i < 4; i++)
#pragma unroll
                for (int j = 0; j < 8; j++)
                    s[i][j] += af[i] * bf[j];
        }
        __syncthreads();   // all threads done reading K before V overwrites KVs

        // Online softmax + write P to shared (transposed: Ps[c][r])
#pragma unroll
        for (int i = 0; i < 4; i++) {
            float mx = -1e30f;
#pragma unroll
            for (int j = 0; j < 8; j++) {
                s[i][j] *= SCALE;
                mx = fmaxf(mx, s[i][j]);
            }
            mx = fmaxf(mx, __shfl_xor_sync(0xffffffffu, mx, 1));
            mx = fmaxf(mx, __shfl_xor_sync(0xffffffffu, mx, 2));
            mx = fmaxf(mx, __shfl_xor_sync(0xffffffffu, mx, 4));
            float mnew = fmaxf(m_i[i], mx);
            float fac  = __expf(m_i[i] - mnew);
            float sum  = 0.f;
#pragma unroll
            for (int j = 0; j < 8; j++) {
                float p = __expf(s[i][j] - mnew);
                Ps[(tc * 8 + j) * 64 + tr * 4 + i] = p;
                sum += p;
            }
            sum += __shfl_xor_sync(0xffffffffu, sum, 1);
            sum += __shfl_xor_sync(0xffffffffu, sum, 2);
            sum += __shfl_xor_sync(0xffffffffu, sum, 4);
            l_i[i] = l_i[i] * fac + sum;
            m_i[i] = mnew;
#pragma unroll
            for (int j = 0; j < 8; j++) acc[i][j] *= fac;
        }

        // Load V tile natural layout (KVs[c][d])
        for (int i = tid; i < 64 * 64; i += 128) {
            int c = i >> 6, d = i & 63;
            KVs[c * 64 + d] = vp[(size_t)(kv0 + c) * QKV_E + d];
        }
        __syncthreads();   // Ps + V ready

        // O += P V    (64x64x64)
#pragma unroll 8
        for (int c = 0; c < 64; c++) {
            float4 a  = *(const float4*)&Ps[c * 64 + tr * 4];
            float4 v0 = *(const float4*)&KVs[c * 64 + tc * 8];
            float4 v1 = *(const float4*)&KVs[c * 64 + tc * 8 + 4];
            float af[4] = {a.x, a.y, a.z, a.w};
            float vf[8] = {v0.x, v0.y, v0.z, v0.w, v1.x, v1.y, v1.z, v1.w};
#pragma unroll
            for (int i = 0; i < 4; i++)
#pragma unroll
                for (int j = 0; j < 8; j++)
                    acc[i][j] += af[i] * vf[j];
        }
    }

    // Epilogue: O / l  ->  og[b, s, h*64 + d]
#pragma unroll
    for (int i = 0; i < 4; i++) {
        float inv = 1.f / l_i[i];
        int r = q0 + tr * 4 + i;
        float* out = og + (size_t)(b * SS + r) * DD + h * HDIM + tc * 8;
        float4 o0 = make_float4(acc[i][0] * inv, acc[i][1] * inv,
                                acc[i][2] * inv, acc[i][3] * inv);
        float4 o1 = make_float4(acc[i][4] * inv, acc[i][5] * inv,
                                acc[i][6] * inv, acc[i][7] * inv);
        *(float4*)(out)     = o0;
        *(float4*)(out + 4) = o1;
    }
}

// ---------------------------------------------------------------------------
extern "C" void kernel_launch(void* const* d_in, const int* in_sizes, int n_in,
                              void* d_out, int out_size)
{
    const float* x     = (const float*)d_in[0];   // [2,2048,1024]
    const float* w_qkv = (const float*)d_in[1];   // [3072,1024]
    const float* w_out = (const float*)d_in[2];   // [1024,1024]
    const float* b_out = (const float*)d_in[3];   // [1024]
    float* out = (float*)d_out;

    void* qkv_p = nullptr;
    void* o_p   = nullptr;
    cudaGetSymbolAddress(&qkv_p, g_qkv);
    cudaGetSymbolAddress(&o_p, g_o);
    float* qkv = (float*)qkv_p;
    float* o   = (float*)o_p;

    // 1) QKV projection: [4096,3072] = x[4096,1024] @ w_qkv[3072,1024]^T
    dim3 g1(QKV_E / 128, MROWS / 128);
    sgemm_nt<<<g1, 256>>>(x, w_qkv, nullptr, qkv, MROWS, QKV_E, DD);

    // 2) Flash attention
    dim3 g2(SS / 64, BB * HH);
    flash64<<<g2, 128>>>(qkv, o);

    // 3) Output projection with bias: [4096,1024] = o @ w_out^T + b_out
    dim3 g3(DD / 128, MROWS / 128);
    sgemm_nt<<<g3, 256>>>(o, w_out, b_out, out, MROWS, DD, DD);
}

// round 3
// speedup vs baseline: 1.3462x; 1.3462x over previous
#include <cuda_runtime.h>
#include <cuda_bf16.h>

// Problem constants
#define BB   2
#define SS   2048
#define DD   1024
#define HH   16
#define HDIM 64
#define MROWS (BB * SS)           // 4096
#define QKV_E (3 * DD)            // 3072
#define SCALE 0.125f              // 1/sqrt(64)

// Scratch (device globals per harness allocation rules)
__device__ __align__(16) float g_qkv[MROWS * QKV_E];   // [b*s][3072]
__device__ __align__(16) float g_o[MROWS * DD];        // [b*s][1024]
// split-bf16 operand buffers
__device__ __align__(16) __nv_bfloat16 g_xhi[MROWS * DD];
__device__ __align__(16) __nv_bfloat16 g_xlo[MROWS * DD];
__device__ __align__(16) __nv_bfloat16 g_wqhi[QKV_E * DD];
__device__ __align__(16) __nv_bfloat16 g_wqlo[QKV_E * DD];
__device__ __align__(16) __nv_bfloat16 g_wohi[DD * DD];
__device__ __align__(16) __nv_bfloat16 g_wolo[DD * DD];
__device__ __align__(16) __nv_bfloat16 g_ohi[MROWS * DD];
__device__ __align__(16) __nv_bfloat16 g_olo[MROWS * DD];

__device__ __forceinline__ unsigned smem_u32(const void* p) {
    unsigned a;
    asm("{ .reg .u64 t; cvta.to.shared.u64 t, %1; cvt.u32.u64 %0, t; }"
        : "=r"(a) : "l"(p));
    return a;
}

// ---------------------------------------------------------------------------
// Split fp32 -> bf16 hi + bf16 lo (exact two-term decomposition)
// ---------------------------------------------------------------------------
__global__ __launch_bounds__(256) void split_bf16(
    const float* __restrict__ x, __nv_bfloat16* __restrict__ hi,
    __nv_bfloat16* __restrict__ lo, int n4)
{
    int i = blockIdx.x * blockDim.x + threadIdx.x;
    if (i >= n4) return;
    float4 v = *(const float4*)(x + i * 4);
    __nv_bfloat16 h0 = __float2bfloat16(v.x);
    __nv_bfloat16 h1 = __float2bfloat16(v.y);
    __nv_bfloat16 h2 = __float2bfloat16(v.z);
    __nv_bfloat16 h3 = __float2bfloat16(v.w);
    __nv_bfloat162 H0; H0.x = h0; H0.y = h1;
    __nv_bfloat162 H1; H1.x = h2; H1.y = h3;
    __nv_bfloat162 L0, L1;
    L0.x = __float2bfloat16(v.x - __bfloat162float(h0));
    L0.y = __float2bfloat16(v.y - __bfloat162float(h1));
    L1.x = __float2bfloat16(v.z - __bfloat162float(h2));
    L1.y = __float2bfloat16(v.w - __bfloat162float(h3));
    ((__nv_bfloat162*)hi)[i * 2 + 0] = H0;
    ((__nv_bfloat162*)hi)[i * 2 + 1] = H1;
    ((__nv_bfloat162*)lo)[i * 2 + 0] = L0;
    ((__nv_bfloat162*)lo)[i * 2 + 1] = L1;
}

// ---------------------------------------------------------------------------
// Split-bf16 NT GEMM on mma.sync (HMMA): C[M,N] = A[M,K] @ B[N,K]^T (+bias)
// 128x128 block, KC=64, 256 threads (8 warps, 2x4 grid of 64x32 warp tiles),
// 2-stage cp.async pipeline, XOR-16B swizzled smem, 3 MMA passes per chunk.
// ---------------------------------------------------------------------------
#define KC 64
#define STAGE_BYTES 65536           // 4 tiles x 128rows x 128B
#define GM_SMEM (2 * STAGE_BYTES)

__device__ __forceinline__ void ldsm4(unsigned addr, unsigned& r0, unsigned& r1,
                                      unsigned& r2, unsigned& r3) {
    asm volatile("ldmatrix.sync.aligned.m8n8.x4.shared.b16 {%0,%1,%2,%3}, [%4];"
                 : "=r"(r0), "=r"(r1), "=r"(r2), "=r"(r3) : "r"(addr));
}
__device__ __forceinline__ void mma16816(float* d, const unsigned* a,
                                         unsigned b0, unsigned b1) {
    asm volatile(
        "mma.sync.aligned.m16n8k16.row.col.f32.bf16.bf16.f32 "
        "{%0,%1,%2,%3}, {%4,%5,%6,%7}, {%8,%9}, {%0,%1,%2,%3};"
        : "+f"(d[0]), "+f"(d[1]), "+f"(d[2]), "+f"(d[3])
        : "r"(a[0]), "r"(a[1]), "r"(a[2]), "r"(a[3]), "r"(b0), "r"(b1));
}

__global__ __launch_bounds__(256) void gemm_mma(
    const __nv_bfloat16* __restrict__ Ahi, const __nv_bfloat16* __restrict__ Alo,
    const __nv_bfloat16* __restrict__ Bhi, const __nv_bfloat16* __restrict__ Blo,
    const float* __restrict__ bias, float* __restrict__ C,
    int M, int N, int K)
{
    extern __shared__ __align__(1024) char sm[];
    const unsigned sb = smem_u32(sm);
    const int tid  = threadIdx.x;
    const int lane = tid & 31;
    const int wid  = tid >> 5;
    const int wm   = wid >> 2;     // 0..1
    const int wn   = wid & 3;      // 0..3
    const int m0   = blockIdx.y * 128;
    const int n0   = blockIdx.x * 128;

    const __nv_bfloat16* src0 = Ahi + (size_t)m0 * K;
    const __nv_bfloat16* src1 = Alo + (size_t)m0 * K;
    const __nv_bfloat16* src2 = Bhi + (size_t)n0 * K;
    const __nv_bfloat16* src3 = Blo + (size_t)n0 * K;

    // per-thread load geometry: 4 x 16B per operand tile per chunk
    const int lr0  = tid >> 3;          // rows tid>>3, +32, +64, +96
    const int lc16 = tid & 7;           // 16B column slot

    float acc[4][4][4];
#pragma unroll
    for (int i = 0; i < 4; i++)
#pragma unroll
        for (int j = 0; j < 4; j++)
#pragma unroll
            for (int q = 0; q < 4; q++) acc[i][j][q] = 0.f;

    const int nch = K / KC;

    // ---- issue loads for a chunk into a stage ----
    auto issue = [&](int cc, int stg) {
        const int k0 = cc * KC;
        const unsigned sbase = sb + stg * STAGE_BYTES;
        const __nv_bfloat16* srcs[4] = {src0, src1, src2, src3};
#pragma unroll
        for (int op = 0; op < 4; op++) {
            const __nv_bfloat16* s = srcs[op];
            const unsigned dst = sbase + op * 16384;
#pragma unroll
            for (int it = 0; it < 4; it++) {
                int r = lr0 + it * 32;
                unsigned saddr = dst + r * 128 + ((lc16 * 16) ^ ((r & 7) << 4));
                const void* g = s + (size_t)r * K + k0 + lc16 * 8;
                asm volatile("cp.async.cg.shared.global [%0], [%1], 16;"
                             :: "r"(saddr), "l"(g));
            }
        }
        asm volatile("cp.async.commit_group;" ::: "memory");
    };

    issue(0, 0);

    for (int cc = 0; cc < nch; cc++) {
        if (cc + 1 < nch) {
            issue(cc + 1, (cc + 1) & 1);
            asm volatile("cp.async.wait_group 1;" ::: "memory");
        } else {
            asm volatile("cp.async.wait_group 0;" ::: "memory");
        }
        __syncthreads();

        const unsigned sbase = sb + (cc & 1) * STAGE_BYTES;
        const unsigned aAddr[2] = {sbase, sbase + 16384};          // A hi, lo
        const unsigned bAddr[2] = {sbase + 32768, sbase + 49152};  // B hi, lo
        const int paA[3] = {0, 0, 1};
        const int paB[3] = {0, 1, 0};

        // precomputed per-thread ldmatrix row offsets
        const int arow = (lane & 15);
        const unsigned acb0 = (lane >> 4) * 16;
        const int bnr  = (lane & 7) + ((lane >> 4) << 3);
        const unsigned bcb0 = ((lane >> 3) & 1) * 16;

#pragma unroll
        for (int p = 0; p < 3; p++) {
            const unsigned Ab = aAddr[paA[p]];
            const unsigned Bb = bAddr[paB[p]];
#pragma unroll
            for (int k16 = 0; k16 < 4; k16++) {
                unsigned a[4][4];
#pragma unroll
                for (int mt = 0; mt < 4; mt++) {
                    int r = wm * 64 + mt * 16 + arow;
                    unsigned cb = k16 * 32 + acb0;
                    unsigned addr = Ab + r * 128 + (cb ^ ((r & 7) << 4));
                    ldsm4(addr, a[mt][0], a[mt][1], a[mt][2], a[mt][3]);
                }
                unsigned b[2][4];
#pragma unroll
                for (int bt = 0; bt < 2; bt++) {
                    int n = wn * 32 + bt * 16 + bnr;
                    unsigned cb = k16 * 32 + bcb0;
                    unsigned addr = Bb + n * 128 + (cb ^ ((n & 7) << 4));
                    ldsm4(addr, b[bt][0], b[bt][1], b[bt][2], b[bt][3]);
                }
#pragma unroll
                for (int mt = 0; mt < 4; mt++)
#pragma unroll
                    for (int nt = 0; nt < 4; nt++)
                        mma16816(acc[mt][nt], a[mt],
                                 b[nt >> 1][(nt & 1) * 2],
                                 b[nt >> 1][(nt & 1) * 2 + 1]);
            }
        }
        __syncthreads();
    }

    // ---- epilogue ----
#pragma unroll
    for (int mt = 0; mt < 4; mt++) {
        int r0 = m0 + wm * 64 + mt * 16 + (lane >> 2);
        int r1 = r0 + 8;
#pragma unroll
        for (int nt = 0; nt < 4; nt++) {
            int c = n0 + wn * 32 + nt * 8 + (lane & 3) * 2;
            float2 bv = make_float2(0.f, 0.f);
            if (bias) bv = *(const float2*)(bias + c);
            float2 v0 = make_float2(acc[mt][nt][0] + bv.x, acc[mt][nt][1] + bv.y);
            float2 v1 = make_float2(acc[mt][nt][2] + bv.x, acc[mt][nt][3] + bv.y);
            *(float2*)(C + (size_t)r0 * N + c) = v0;
            *(float2*)(C + (size_t)r1 * N + c) = v1;
        }
    }
}

// ---------------------------------------------------------------------------
// Flash attention, fp32 (unchanged; known-good). One block per (b*h, 64-q).
// ---------------------------------------------------------------------------
__global__ __launch_bounds__(128) void flash64(
    const float* __restrict__ qkv, float* __restrict__ og)
{
    __shared__ float Qs[64 * 64];
    __shared__ float KVs[64 * 64];
    __shared__ float Ps[64 * 64];

    const int tid = threadIdx.x;
    const int tr  = tid >> 3;
    const int tc  = tid & 7;
    const int q0  = blockIdx.x * 64;
    const int b   = blockIdx.y >> 4;
    const int h   = blockIdx.y & 15;

    const float* qp = qkv + (size_t)b * SS * QKV_E + DD     + h * HDIM;
    const float* kp = qkv + (size_t)b * SS * QKV_E + 2 * DD + h * HDIM;
    const float* vp = qkv + (size_t)b * SS * QKV_E          + h * HDIM;

    for (int i = tid; i < 64 * 64; i += 128) {
        int r = i >> 6, d = i & 63;
        Qs[d * 64 + (r ^ ((d & 7) << 3))] = qp[(size_t)(q0 + r) * QKV_E + d];
    }

    float acc[4][8];
    float m_i[4], l_i[4];
#pragma unroll
    for (int i = 0; i < 4; i++) {
        m_i[i] = -1e30f; l_i[i] = 0.f;
#pragma unroll
        for (int j = 0; j < 8; j++) acc[i][j] = 0.f;
    }

    for (int kv0 = 0; kv0 < SS; kv0 += 64) {
        __syncthreads();
        for (int i = tid; i < 64 * 64; i += 128) {
            int c = i >> 6, d = i & 63;
            KVs[d * 64 + (c ^ ((d & 7) << 3))] =
                kp[(size_t)(kv0 + c) * QKV_E + d];
        }
        __syncthreads();

        float s[4][8];
#pragma unroll
        for (int i = 0; i < 4; i++)
#pragma unroll
            for (int j = 0; j < 8; j++) s[i][j] = 0.f;

#pragma unroll 8
        for (int d = 0; d < 64; d++) {
            const int sw = (d & 7) << 3;
            float4 a  = *(const float4*)&Qs[d * 64 + ((tr * 4) ^ sw)];
            int    bo = d * 64 + ((tc * 8) ^ sw);
            float4 b0 = *(const float4*)&KVs[bo];
            float4 b1 = *(const float4*)&KVs[bo + 4];
            float af[4] = {a.x, a.y, a.z, a.w};
            float bf[8] = {b0.x, b0.y, b0.z, b0.w, b1.x, b1.y, b1.z, b1.w};
#pragma unroll
            for (int i = 0; i < 4; i++)
#pragma unroll
                for (int j = 0; j < 8; j++)
                    s[i][j] += af[i] * bf[j];
        }
        __syncthreads();

#pragma unroll
        for (int i = 0; i < 4; i++) {
            float mx = -1e30f;
#pragma unroll
            for (int j = 0; j < 8; j++) {
                s[i][j] *= SCALE;
                mx = fmaxf(mx, s[i][j]);
            }
            mx = fmaxf(mx, __shfl_xor_sync(0xffffffffu, mx, 1));
            mx = fmaxf(mx, __shfl_xor_sync(0xffffffffu, mx, 2));
            mx = fmaxf(mx, __shfl_xor_sync(0xffffffffu, mx, 4));
            float mnew = fmaxf(m_i[i], mx);
            float fac  = __expf(m_i[i] - mnew);
            float sum  = 0.f;
#pragma unroll
            for (int j = 0; j < 8; j++) {
                float p = __expf(s[i][j] - mnew);
                Ps[(tc * 8 + j) * 64 + tr * 4 + i] = p;
                sum += p;
            }
            sum += __shfl_xor_sync(0xffffffffu, sum, 1);
            sum += __shfl_xor_sync(0xffffffffu, sum, 2);
            sum += __shfl_xor_sync(0xffffffffu, sum, 4);
            l_i[i] = l_i[i] * fac + sum;
            m_i[i] = mnew;
#pragma unroll
            for (int j = 0; j < 8; j++) acc[i][j] *= fac;
        }

        for (int i = tid; i < 64 * 64; i += 128) {
            int c = i >> 6, d = i & 63;
            KVs[c * 64 + d] = vp[(size_t)(kv0 + c) * QKV_E + d];
        }
        __syncthreads();

#pragma unroll 8
        for (int c = 0; c < 64; c++) {
            float4 a  = *(const float4*)&Ps[c * 64 + tr * 4];
            float4 v0 = *(const float4*)&KVs[c * 64 + tc * 8];
            float4 v1 = *(const float4*)&KVs[c * 64 + tc * 8 + 4];
            float af[4] = {a.x, a.y, a.z, a.w};
            float vf[8] = {v0.x, v0.y, v0.z, v0.w, v1.x, v1.y, v1.z, v1.w};
#pragma unroll
            for (int i = 0; i < 4; i++)
#pragma unroll
                for (int j = 0; j < 8; j++)
                    acc[i][j] += af[i] * vf[j];
        }
    }

#pragma unroll
    for (int i = 0; i < 4; i++) {
        float inv = 1.f / l_i[i];
        int r = q0 + tr * 4 + i;
        float* out = og + (size_t)(b * SS + r) * DD + h * HDIM + tc * 8;
        float4 o0 = make_float4(acc[i][0] * inv, acc[i][1] * inv,
                                acc[i][2] * inv, acc[i][3] * inv);
        float4 o1 = make_float4(acc[i][4] * inv, acc[i][5] * inv,
                                acc[i][6] * inv, acc[i][7] * inv);
        *(float4*)(out)     = o0;
        *(float4*)(out + 4) = o1;
    }
}

// ---------------------------------------------------------------------------
extern "C" void kernel_launch(void* const* d_in, const int* in_sizes, int n_in,
                              void* d_out, int out_size)
{
    const float* x     = (const float*)d_in[0];   // [2,2048,1024]
    const float* w_qkv = (const float*)d_in[1];   // [3072,1024]
    const float* w_out = (const float*)d_in[2];   // [1024,1024]
    const float* b_out = (const float*)d_in[3];   // [1024]
    float* out = (float*)d_out;

    void *qkv_p, *o_p, *xhi_p, *xlo_p, *wqhi_p, *wqlo_p, *wohi_p, *wolo_p,
         *ohi_p, *olo_p;
    cudaGetSymbolAddress(&qkv_p, g_qkv);
    cudaGetSymbolAddress(&o_p, g_o);
    cudaGetSymbolAddress(&xhi_p, g_xhi);
    cudaGetSymbolAddress(&xlo_p, g_xlo);
    cudaGetSymbolAddress(&wqhi_p, g_wqhi);
    cudaGetSymbolAddress(&wqlo_p, g_wqlo);
    cudaGetSymbolAddress(&wohi_p, g_wohi);
    cudaGetSymbolAddress(&wolo_p, g_wolo);
    cudaGetSymbolAddress(&ohi_p, g_ohi);
    cudaGetSymbolAddress(&olo_p, g_olo);
    float* qkv = (float*)qkv_p;
    float* o   = (float*)o_p;

    cudaFuncSetAttribute(gemm_mma,
                         cudaFuncAttributeMaxDynamicSharedMemorySize, GM_SMEM);

    // 0) split inputs into bf16 hi/lo
    int n4x = MROWS * DD / 4;
    split_bf16<<<(n4x + 255) / 256, 256>>>(x, (__nv_bfloat16*)xhi_p,
                                           (__nv_bfloat16*)xlo_p, n4x);
    int n4q = QKV_E * DD / 4;
    split_bf16<<<(n4q + 255) / 256, 256>>>(w_qkv, (__nv_bfloat16*)wqhi_p,
                                           (__nv_bfloat16*)wqlo_p, n4q);
    int n4w = DD * DD / 4;
    split_bf16<<<(n4w + 255) / 256, 256>>>(w_out, (__nv_bfloat16*)wohi_p,
                                           (__nv_bfloat16*)wolo_p, n4w);

    // 1) QKV projection: [4096,3072] = x @ w_qkv^T   (HMMA split-bf16)
    dim3 g1(QKV_E / 128, MROWS / 128);
    gemm_mma<<<g1, 256, GM_SMEM>>>(
        (const __nv_bfloat16*)xhi_p, (const __nv_bfloat16*)xlo_p,
        (const __nv_bfloat16*)wqhi_p, (const __nv_bfloat16*)wqlo_p,
        nullptr, qkv, MROWS, QKV_E, DD);

    // 2) Flash attention (fp32)
    dim3 g2(SS / 64, BB * HH);
    flash64<<<g2, 128>>>(qkv, o);

    // 2b) split attention output
    split_bf16<<<(n4x + 255) / 256, 256>>>(o, (__nv_bfloat16*)ohi_p,
                                           (__nv_bfloat16*)olo_p, n4x);

    // 3) Output projection with bias   (HMMA split-bf16)
    dim3 g3(DD / 128, MROWS / 128);
    gemm_mma<<<g3, 256, GM_SMEM>>>(
        (const __nv_bfloat16*)ohi_p, (const __nv_bfloat16*)olo_p,
        (const __nv_bfloat16*)wohi_p, (const __nv_bfloat16*)wolo_p,
        b_out, out, MROWS, DD, DD);
}

// round 4
// speedup vs baseline: 3.6555x; 2.7153x over previous
#include <cuda_runtime.h>
#include <cuda_bf16.h>
#include <cuda_fp16.h>

// Problem constants
#define BB   2
#define SS   2048
#define DD   1024
#define HH   16
#define HDIM 64
#define MROWS (BB * SS)           // 4096
#define QKV_E (3 * DD)            // 3072
#define SCALE 0.125f              // 1/sqrt(64)

// Scratch (device globals per harness allocation rules)
__device__ __align__(16) __nv_bfloat16 g_xhi[MROWS * DD];
__device__ __align__(16) __nv_bfloat16 g_xlo[MROWS * DD];
__device__ __align__(16) __nv_bfloat16 g_wqhi[QKV_E * DD];
__device__ __align__(16) __nv_bfloat16 g_wqlo[QKV_E * DD];
__device__ __align__(16) __nv_bfloat16 g_wohi[DD * DD];
__device__ __align__(16) __nv_bfloat16 g_wolo[DD * DD];
__device__ __align__(16) __nv_bfloat16 g_ohi[MROWS * DD];
__device__ __align__(16) __nv_bfloat16 g_olo[MROWS * DD];
// fp16 split q/k/v in [b][h][s][64] layout (q pre-scaled by SCALE)
#define QKVN (BB * HH * SS * HDIM)
__device__ __align__(16) __half g_qh[QKVN];
__device__ __align__(16) __half g_ql[QKVN];
__device__ __align__(16) __half g_kh[QKVN];
__device__ __align__(16) __half g_kl[QKVN];
__device__ __align__(16) __half g_vh[QKVN];
__device__ __align__(16) __half g_vl[QKVN];

__device__ __forceinline__ unsigned smem_u32(const void* p) {
    unsigned a;
    asm("{ .reg .u64 t; cvta.to.shared.u64 t, %1; cvt.u32.u64 %0, t; }"
        : "=r"(a) : "l"(p));
    return a;
}

// ---------------------------------------------------------------------------
// Split fp32 -> bf16 hi + bf16 lo
// ---------------------------------------------------------------------------
__global__ __launch_bounds__(256) void split_bf16(
    const float* __restrict__ x, __nv_bfloat16* __restrict__ hi,
    __nv_bfloat16* __restrict__ lo, int n4)
{
    int i = blockIdx.x * blockDim.x + threadIdx.x;
    if (i >= n4) return;
    float4 v = *(const float4*)(x + i * 4);
    __nv_bfloat16 h0 = __float2bfloat16(v.x);
    __nv_bfloat16 h1 = __float2bfloat16(v.y);
    __nv_bfloat16 h2 = __float2bfloat16(v.z);
    __nv_bfloat16 h3 = __float2bfloat16(v.w);
    __nv_bfloat162 H0; H0.x = h0; H0.y = h1;
    __nv_bfloat162 H1; H1.x = h2; H1.y = h3;
    __nv_bfloat162 L0, L1;
    L0.x = __float2bfloat16(v.x - __bfloat162float(h0));
    L0.y = __float2bfloat16(v.y - __bfloat162float(h1));
    L1.x = __float2bfloat16(v.z - __bfloat162float(h2));
    L1.y = __float2bfloat16(v.w - __bfloat162float(h3));
    ((__nv_bfloat162*)hi)[i * 2 + 0] = H0;
    ((__nv_bfloat162*)hi)[i * 2 + 1] = H1;
    ((__nv_bfloat162*)lo)[i * 2 + 0] = L0;
    ((__nv_bfloat162*)lo)[i * 2 + 1] = L1;
}

// ---------------------------------------------------------------------------
// MMA primitives
// ---------------------------------------------------------------------------
__device__ __forceinline__ void ldsm4(unsigned addr, unsigned& r0, unsigned& r1,
                                      unsigned& r2, unsigned& r3) {
    asm volatile("ldmatrix.sync.aligned.m8n8.x4.shared.b16 {%0,%1,%2,%3}, [%4];"
                 : "=r"(r0), "=r"(r1), "=r"(r2), "=r"(r3) : "r"(addr));
}
__device__ __forceinline__ void ldsm4t(unsigned addr, unsigned& r0, unsigned& r1,
                                       unsigned& r2, unsigned& r3) {
    asm volatile("ldmatrix.sync.aligned.m8n8.x4.trans.shared.b16 {%0,%1,%2,%3}, [%4];"
                 : "=r"(r0), "=r"(r1), "=r"(r2), "=r"(r3) : "r"(addr));
}
__device__ __forceinline__ void mma_bf(float* d, const unsigned* a,
                                       unsigned b0, unsigned b1) {
    asm volatile(
        "mma.sync.aligned.m16n8k16.row.col.f32.bf16.bf16.f32 "
        "{%0,%1,%2,%3}, {%4,%5,%6,%7}, {%8,%9}, {%0,%1,%2,%3};"
        : "+f"(d[0]), "+f"(d[1]), "+f"(d[2]), "+f"(d[3])
        : "r"(a[0]), "r"(a[1]), "r"(a[2]), "r"(a[3]), "r"(b0), "r"(b1));
}
__device__ __forceinline__ void mma_fp(float* d, const unsigned* a,
                                       unsigned b0, unsigned b1) {
    asm volatile(
        "mma.sync.aligned.m16n8k16.row.col.f32.f16.f16.f32 "
        "{%0,%1,%2,%3}, {%4,%5,%6,%7}, {%8,%9}, {%0,%1,%2,%3};"
        : "+f"(d[0]), "+f"(d[1]), "+f"(d[2]), "+f"(d[3])
        : "r"(a[0]), "r"(a[1]), "r"(a[2]), "r"(a[3]), "r"(b0), "r"(b1));
}

// ---------------------------------------------------------------------------
// Split-bf16 NT GEMM (HMMA): C[M,N] = A @ B^T (+bias). 128x128, KC=64,
// 256 thr, 2-stage cp.async, 3 passes. MODE: 0 = write fp32 C;
// 1 = QKV epilogue (write split fp16 q/k/v, q pre-scaled).
// ---------------------------------------------------------------------------
#define KC 64
#define STAGE_BYTES 65536
#define GM_SMEM (2 * STAGE_BYTES)

template <int MODE>
__global__ __launch_bounds__(256) void gemm_mma(
    const __nv_bfloat16* __restrict__ Ahi, const __nv_bfloat16* __restrict__ Alo,
    const __nv_bfloat16* __restrict__ Bhi, const __nv_bfloat16* __restrict__ Blo,
    const float* __restrict__ bias, float* __restrict__ C,
    __half* __restrict__ qh, __half* __restrict__ ql,
    __half* __restrict__ kh, __half* __restrict__ kl,
    __half* __restrict__ vh, __half* __restrict__ vl,
    int M, int N, int K)
{
    extern __shared__ __align__(1024) char sm[];
    const unsigned sb = smem_u32(sm);
    const int tid  = threadIdx.x;
    const int lane = tid & 31;
    const int wid  = tid >> 5;
    const int wm   = wid >> 2;
    const int wn   = wid & 3;
    const int m0   = blockIdx.y * 128;
    const int n0   = blockIdx.x * 128;

    const __nv_bfloat16* src0 = Ahi + (size_t)m0 * K;
    const __nv_bfloat16* src1 = Alo + (size_t)m0 * K;
    const __nv_bfloat16* src2 = Bhi + (size_t)n0 * K;
    const __nv_bfloat16* src3 = Blo + (size_t)n0 * K;

    const int lr0  = tid >> 3;
    const int lc16 = tid & 7;

    float acc[4][4][4];
#pragma unroll
    for (int i = 0; i < 4; i++)
#pragma unroll
        for (int j = 0; j < 4; j++)
#pragma unroll
            for (int q = 0; q < 4; q++) acc[i][j][q] = 0.f;

    const int nch = K / KC;

    auto issue = [&](int cc, int stg) {
        const int k0 = cc * KC;
        const unsigned sbase = sb + stg * STAGE_BYTES;
        const __nv_bfloat16* srcs[4] = {src0, src1, src2, src3};
#pragma unroll
        for (int op = 0; op < 4; op++) {
            const __nv_bfloat16* s = srcs[op];
            const unsigned dst = sbase + op * 16384;
#pragma unroll
            for (int it = 0; it < 4; it++) {
                int r = lr0 + it * 32;
                unsigned saddr = dst + r * 128 + ((lc16 * 16) ^ ((r & 7) << 4));
                const void* g = s + (size_t)r * K + k0 + lc16 * 8;
                asm volatile("cp.async.cg.shared.global [%0], [%1], 16;"
                             :: "r"(saddr), "l"(g));
            }
        }
        asm volatile("cp.async.commit_group;" ::: "memory");
    };

    issue(0, 0);

    for (int cc = 0; cc < nch; cc++) {
        if (cc + 1 < nch) {
            issue(cc + 1, (cc + 1) & 1);
            asm volatile("cp.async.wait_group 1;" ::: "memory");
        } else {
            asm volatile("cp.async.wait_group 0;" ::: "memory");
        }
        __syncthreads();

        const unsigned sbase = sb + (cc & 1) * STAGE_BYTES;
        const unsigned aAddr[2] = {sbase, sbase + 16384};
        const unsigned bAddr[2] = {sbase + 32768, sbase + 49152};
        const int paA[3] = {0, 0, 1};
        const int paB[3] = {0, 1, 0};

        const int arow = (lane & 15);
        const unsigned acb0 = (lane >> 4) * 16;
        const int bnr  = (lane & 7) + ((lane >> 4) << 3);
        const unsigned bcb0 = ((lane >> 3) & 1) * 16;

#pragma unroll
        for (int p = 0; p < 3; p++) {
            const unsigned Ab = aAddr[paA[p]];
            const unsigned Bb = bAddr[paB[p]];
#pragma unroll
            for (int k16 = 0; k16 < 4; k16++) {
                unsigned a[4][4];
#pragma unroll
                for (int mt = 0; mt < 4; mt++) {
                    int r = wm * 64 + mt * 16 + arow;
                    unsigned cb = k16 * 32 + acb0;
                    unsigned addr = Ab + r * 128 + (cb ^ ((r & 7) << 4));
                    ldsm4(addr, a[mt][0], a[mt][1], a[mt][2], a[mt][3]);
                }
                unsigned b[2][4];
#pragma unroll
                for (int bt = 0; bt < 2; bt++) {
                    int n = wn * 32 + bt * 16 + bnr;
                    unsigned cb = k16 * 32 + bcb0;
                    unsigned addr = Bb + n * 128 + (cb ^ ((n & 7) << 4));
                    ldsm4(addr, b[bt][0], b[bt][1], b[bt][2], b[bt][3]);
                }
#pragma unroll
                for (int mt = 0; mt < 4; mt++)
#pragma unroll
                    for (int nt = 0; nt < 4; nt++)
                        mma_bf(acc[mt][nt], a[mt],
                               b[nt >> 1][(nt & 1) * 2],
                               b[nt >> 1][(nt & 1) * 2 + 1]);
            }
        }
        __syncthreads();
    }

    // ---- epilogue ----
#pragma unroll
    for (int mt = 0; mt < 4; mt++) {
        int r0 = m0 + wm * 64 + mt * 16 + (lane >> 2);
#pragma unroll
        for (int nt = 0; nt < 4; nt++) {
            int c = n0 + wn * 32 + nt * 8 + (lane & 3) * 2;
            if (MODE == 0) {
                float2 bv = make_float2(0.f, 0.f);
                if (bias) bv = *(const float2*)(bias + c);
                *(float2*)(C + (size_t)r0 * N + c) =
                    make_float2(acc[mt][nt][0] + bv.x, acc[mt][nt][1] + bv.y);
                *(float2*)(C + (size_t)(r0 + 8) * N + c) =
                    make_float2(acc[mt][nt][2] + bv.x, acc[mt][nt][3] + bv.y);
            } else {
                int which = c >> 10;
                int rem   = c & 1023;
                int h     = rem >> 6;
                int d     = rem & 63;
                __half* HI = (which == 0) ? vh : (which == 1) ? qh : kh;
                __half* LO = (which == 0) ? vl : (which == 1) ? ql : kl;
#pragma unroll
                for (int half_ = 0; half_ < 2; half_++) {
                    int row = r0 + half_ * 8;
                    float v0 = acc[mt][nt][half_ * 2 + 0];
                    float v1 = acc[mt][nt][half_ * 2 + 1];
                    if (which == 1) { v0 *= SCALE; v1 *= SCALE; }
                    int b = row >> 11, s = row & 2047;
                    size_t idx = ((size_t)(b * HH + h) * SS + s) * HDIM + d;
                    __half h0 = __float2half_rn(v0);
                    __half h1 = __float2half_rn(v1);
                    __half l0 = __float2half_rn(v0 - __half2float(h0));
                    __half l1 = __float2half_rn(v1 - __half2float(h1));
                    __half2 Hp; Hp.x = h0; Hp.y = h1;
                    __half2 Lp; Lp.x = l0; Lp.y = l1;
                    *(__half2*)(HI + idx) = Hp;
                    *(__half2*)(LO + idx) = Lp;
                }
            }
        }
    }
}

// ---------------------------------------------------------------------------
// Tensor-core flash attention (split-fp16, 3-pass QK^T and PV).
// Block: 128 q rows, 8 warps (16 rows each), BK=64, 2-stage cp.async KV.
// Writes bf16 hi/lo output for the out-projection.
// ---------------------------------------------------------------------------
#define FA_SMEM (32768 + 2 * 32768)   // Qhi/Qlo + 2 KV stages = 96KB

__global__ __launch_bounds__(256) void flash_mma(
    const __half* __restrict__ Qhi, const __half* __restrict__ Qlo,
    const __half* __restrict__ Khi, const __half* __restrict__ Klo,
    const __half* __restrict__ Vhi, const __half* __restrict__ Vlo,
    __nv_bfloat16* __restrict__ Ohi, __nv_bfloat16* __restrict__ Olo)
{
    extern __shared__ __align__(1024) char sm[];
    const unsigned sb = smem_u32(sm);
    const int tid  = threadIdx.x;
    const int lane = tid & 31;
    const int wid  = tid >> 5;
    const int q0   = blockIdx.x * 128;
    const int bh   = blockIdx.y;          // b*16 + h

    const size_t base = (size_t)bh * SS * HDIM;
    const __half* qhg = Qhi + base;
    const __half* qlg = Qlo + base;
    const __half* khg = Khi + base;
    const __half* klg = Klo + base;
    const __half* vhg = Vhi + base;
    const __half* vlg = Vlo + base;

    const unsigned sQh = sb, sQl = sb + 16384;
    const unsigned sStage = sb + 32768;

    // ---- load Q tiles (128 x 64 fp16, hi+lo) ----
#pragma unroll
    for (int it = 0; it < 4; it++) {
        int idx = it * 256 + tid;          // 0..1023
        int r   = idx >> 3;                // 0..127
        int c16 = idx & 7;
        unsigned off = r * 128 + ((c16 * 16) ^ ((r & 7) << 4));
        const void* gh = qhg + (size_t)(q0 + r) * HDIM + c16 * 8;
        const void* gl = qlg + (size_t)(q0 + r) * HDIM + c16 * 8;
        asm volatile("cp.async.cg.shared.global [%0], [%1], 16;"
                     :: "r"(sQh + off), "l"(gh));
        asm volatile("cp.async.cg.shared.global [%0], [%1], 16;"
                     :: "r"(sQl + off), "l"(gl));
    }
    asm volatile("cp.async.commit_group;" ::: "memory");

    auto issue_kv = [&](int i, int stg) {
        const int kv0 = i * 64;
        const unsigned s0 = sStage + stg * 32768;
        const __half* srcs[4] = {khg, klg, vhg, vlg};
#pragma unroll
        for (int op = 0; op < 4; op++) {
            const unsigned dst = s0 + op * 8192;
#pragma unroll
            for (int it = 0; it < 2; it++) {
                int idx = it * 256 + tid;  // 0..511
                int r   = idx >> 3;        // 0..63
                int c16 = idx & 7;
                unsigned saddr = dst + r * 128 + ((c16 * 16) ^ ((r & 7) << 4));
                const void* g = srcs[op] + (size_t)(kv0 + r) * HDIM + c16 * 8;
                asm volatile("cp.async.cg.shared.global [%0], [%1], 16;"
                             :: "r"(saddr), "l"(g));
            }
        }
        asm volatile("cp.async.commit_group;" ::: "memory");
    };

    issue_kv(0, 0);
    asm volatile("cp.async.wait_group 1;" ::: "memory");   // Q done
    __syncthreads();

    // ---- build persistent Q a-frags ----
    unsigned qhf[4][4], qlf[4][4];
    {
        const int arow = wid * 16 + (lane & 15);
        const unsigned acb0 = (lane >> 4) * 16;
#pragma unroll
        for (int ks = 0; ks < 4; ks++) {
            unsigned cb = ks * 32 + acb0;
            unsigned off = arow * 128 + (cb ^ ((arow & 7) << 4));
            ldsm4(sQh + off, qhf[ks][0], qhf[ks][1], qhf[ks][2], qhf[ks][3]);
            ldsm4(sQl + off, qlf[ks][0], qlf[ks][1], qlf[ks][2], qlf[ks][3]);
        }
    }

    float o[8][4];
#pragma unroll
    for (int i = 0; i < 8; i++)
#pragma unroll
        for (int j = 0; j < 4; j++) o[i][j] = 0.f;
    float m0r = -1e30f, m1r = -1e30f, l0r = 0.f, l1r = 0.f;

    const int bnr  = (lane & 7) + ((lane >> 4) << 3);
    const unsigned bcb0 = ((lane >> 3) & 1) * 16;
    const int vrow0 = (lane & 7) + (((lane >> 3) & 1) << 3);
    const unsigned vcb = (lane >> 4) * 16;

    const int NIT = SS / 64;   // 32
    for (int cc = 0; cc < NIT; cc++) {
        if (cc + 1 < NIT) {
            issue_kv(cc + 1, (cc + 1) & 1);
            asm volatile("cp.async.wait_group 1;" ::: "memory");
        } else {
            asm volatile("cp.async.wait_group 0;" ::: "memory");
        }
        __syncthreads();

        const unsigned st = sStage + (cc & 1) * 32768;
        const unsigned sKh = st, sKl = st + 8192;
        const unsigned sVh = st + 16384, sVl = st + 24576;

        // ---- S = Q K^T (3-pass split-fp16), s[nt][4] ----
        float s[8][4];
#pragma unroll
        for (int i = 0; i < 8; i++)
#pragma unroll
            for (int j = 0; j < 4; j++) s[i][j] = 0.f;

#pragma unroll
        for (int ks = 0; ks < 4; ks++) {
#pragma unroll
            for (int g = 0; g < 4; g++) {
                int r = g * 16 + bnr;
                unsigned cb = ks * 32 + bcb0;
                unsigned off = r * 128 + (cb ^ ((r & 7) << 4));
                unsigned h0, h1, h2, h3, l0, l1, l2, l3;
                ldsm4(sKh + off, h0, h1, h2, h3);
                ldsm4(sKl + off, l0, l1, l2, l3);
                mma_fp(s[2 * g],     qhf[ks], h0, h1);
                mma_fp(s[2 * g],     qhf[ks], l0, l1);
                mma_fp(s[2 * g],     qlf[ks], h0, h1);
                mma_fp(s[2 * g + 1], qhf[ks], h2, h3);
                mma_fp(s[2 * g + 1], qhf[ks], l2, l3);
                mma_fp(s[2 * g + 1], qlf[ks], h2, h3);
            }
        }

        // ---- online softmax (scale pre-applied to Q) ----
        float mx0 = -1e30f, mx1 = -1e30f;
#pragma unroll
        for (int nt = 0; nt < 8; nt++) {
            mx0 = fmaxf(mx0, fmaxf(s[nt][0], s[nt][1]));
            mx1 = fmaxf(mx1, fmaxf(s[nt][2], s[nt][3]));
        }
        mx0 = fmaxf(mx0, __shfl_xor_sync(0xffffffffu, mx0, 1));
        mx0 = fmaxf(mx0, __shfl_xor_sync(0xffffffffu, mx0, 2));
        mx1 = fmaxf(mx1, __shfl_xor_sync(0xffffffffu, mx1, 1));
        mx1 = fmaxf(mx1, __shfl_xor_sync(0xffffffffu, mx1, 2));
        float mn0 = fmaxf(m0r, mx0), mn1 = fmaxf(m1r, mx1);
        float f0 = __expf(m0r - mn0), f1 = __expf(m1r - mn1);
        float sum0 = 0.f, sum1 = 0.f;
#pragma unroll
        for (int nt = 0; nt < 8; nt++) {
            s[nt][0] = __expf(s[nt][0] - mn0);
            s[nt][1] = __expf(s[nt][1] - mn0);
            s[nt][2] = __expf(s[nt][2] - mn1);
            s[nt][3] = __expf(s[nt][3] - mn1);
            sum0 += s[nt][0] + s[nt][1];
            sum1 += s[nt][2] + s[nt][3];
        }
        sum0 += __shfl_xor_sync(0xffffffffu, sum0, 1);
        sum0 += __shfl_xor_sync(0xffffffffu, sum0, 2);
        sum1 += __shfl_xor_sync(0xffffffffu, sum1, 1);
        sum1 += __shfl_xor_sync(0xffffffffu, sum1, 2);
        l0r = l0r * f0 + sum0;
        l1r = l1r * f1 + sum1;
        m0r = mn0; m1r = mn1;
#pragma unroll
        for (int nd = 0; nd < 8; nd++) {
            o[nd][0] *= f0; o[nd][1] *= f0;
            o[nd][2] *= f1; o[nd][3] *= f1;
        }

        // ---- O += P V (3-pass split-fp16) ----
#pragma unroll
        for (int kk = 0; kk < 4; kk++) {
            // P a-frags (hi/lo) for kv cols [kk*16, kk*16+16)
            float2 p00 = make_float2(s[2 * kk][0], s[2 * kk][1]);
            float2 p01 = make_float2(s[2 * kk][2], s[2 * kk][3]);
            float2 p10 = make_float2(s[2 * kk + 1][0], s[2 * kk + 1][1]);
            float2 p11 = make_float2(s[2 * kk + 1][2], s[2 * kk + 1][3]);
            __half2 H0 = __float22half2_rn(p00);
            __half2 H1 = __float22half2_rn(p01);
            __half2 H2 = __float22half2_rn(p10);
            __half2 H3 = __float22half2_rn(p11);
            float2 r0 = __half22float2(H0), r1 = __half22float2(H1);
            float2 r2 = __half22float2(H2), r3 = __half22float2(H3);
            __half2 L0 = __float22half2_rn(make_float2(p00.x - r0.x, p00.y - r0.y));
            __half2 L1 = __float22half2_rn(make_float2(p01.x - r1.x, p01.y - r1.y));
            __half2 L2 = __float22half2_rn(make_float2(p10.x - r2.x, p10.y - r2.y));
            __half2 L3 = __float22half2_rn(make_float2(p11.x - r3.x, p11.y - r3.y));
            unsigned pah[4] = {*(unsigned*)&H0, *(unsigned*)&H1,
                               *(unsigned*)&H2, *(unsigned*)&H3};
            unsigned pal[4] = {*(unsigned*)&L0, *(unsigned*)&L1,
                               *(unsigned*)&L2, *(unsigned*)&L3};

#pragma unroll
            for (int np = 0; np < 4; np++) {    // d-ntile pairs
                int r = kk * 16 + vrow0;
                unsigned cb = (np * 2) * 16 + vcb;
                unsigned off = r * 128 + (cb ^ ((r & 7) << 4));
                unsigned vh0, vh1, vh2, vh3, vl0, vl1, vl2, vl3;
                ldsm4t(sVh + off, vh0, vh1, vh2, vh3);
                ldsm4t(sVl + off, vl0, vl1, vl2, vl3);
                mma_fp(o[2 * np],     pah, vh0, vh1);
                mma_fp(o[2 * np],     pal, vh0, vh1);
                mma_fp(o[2 * np],     pah, vl0, vl1);
                mma_fp(o[2 * np + 1], pah, vh2, vh3);
                mma_fp(o[2 * np + 1], pal, vh2, vh3);
                mma_fp(o[2 * np + 1], pah, vl2, vl3);
            }
        }
        __syncthreads();
    }

    // ---- epilogue: normalize + write bf16 hi/lo [4096][1024] ----
    const float inv0 = 1.f / l0r, inv1 = 1.f / l1r;
    const int b = bh >> 4, h = bh & 15;
    const int row0 = q0 + wid * 16 + (lane >> 2);
    const int grow0 = b * SS + row0;
    const int col0 = h * HDIM + (lane & 3) * 2;
#pragma unroll
    for (int nd = 0; nd < 8; nd++) {
        int c = col0 + nd * 8;
#pragma unroll
        for (int half_ = 0; half_ < 2; half_++) {
            float v0 = o[nd][half_ * 2 + 0] * (half_ ? inv1 : inv0);
            float v1 = o[nd][half_ * 2 + 1] * (half_ ? inv1 : inv0);
            size_t idx = (size_t)(grow0 + half_ * 8) * DD + c;
            __nv_bfloat16 h0 = __float2bfloat16(v0);
            __nv_bfloat16 h1 = __float2bfloat16(v1);
            __nv_bfloat162 Hp; Hp.x = h0; Hp.y = h1;
            __nv_bfloat162 Lp;
            Lp.x = __float2bfloat16(v0 - __bfloat162float(h0));
            Lp.y = __float2bfloat16(v1 - __bfloat162float(h1));
            *(__nv_bfloat162*)(Ohi + idx) = Hp;
            *(__nv_bfloat162*)(Olo + idx) = Lp;
        }
    }
}

// ---------------------------------------------------------------------------
extern "C" void kernel_launch(void* const* d_in, const int* in_sizes, int n_in,
                              void* d_out, int out_size)
{
    const float* x     = (const float*)d_in[0];
    const float* w_qkv = (const float*)d_in[1];
    const float* w_out = (const float*)d_in[2];
    const float* b_out = (const float*)d_in[3];
    float* out = (float*)d_out;

    void *xhi_p, *xlo_p, *wqhi_p, *wqlo_p, *wohi_p, *wolo_p, *ohi_p, *olo_p;
    void *qh_p, *ql_p, *kh_p, *kl_p, *vh_p, *vl_p;
    cudaGetSymbolAddress(&xhi_p, g_xhi);
    cudaGetSymbolAddress(&xlo_p, g_xlo);
    cudaGetSymbolAddress(&wqhi_p, g_wqhi);
    cudaGetSymbolAddress(&wqlo_p, g_wqlo);
    cudaGetSymbolAddress(&wohi_p, g_wohi);
    cudaGetSymbolAddress(&wolo_p, g_wolo);
    cudaGetSymbolAddress(&ohi_p, g_ohi);
    cudaGetSymbolAddress(&olo_p, g_olo);
    cudaGetSymbolAddress(&qh_p, g_qh);
    cudaGetSymbolAddress(&ql_p, g_ql);
    cudaGetSymbolAddress(&kh_p, g_kh);
    cudaGetSymbolAddress(&kl_p, g_kl);
    cudaGetSymbolAddress(&vh_p, g_vh);
    cudaGetSymbolAddress(&vl_p, g_vl);

    cudaFuncSetAttribute(gemm_mma<0>,
                         cudaFuncAttributeMaxDynamicSharedMemorySize, GM_SMEM);
    cudaFuncSetAttribute(gemm_mma<1>,
                         cudaFuncAttributeMaxDynamicSharedMemorySize, GM_SMEM);
    cudaFuncSetAttribute(flash_mma,
                         cudaFuncAttributeMaxDynamicSharedMemorySize, FA_SMEM);

    // 0) split fp32 inputs into bf16 hi/lo
    int n4x = MROWS * DD / 4;
    split_bf16<<<(n4x + 255) / 256, 256>>>(x, (__nv_bfloat16*)xhi_p,
                                           (__nv_bfloat16*)xlo_p, n4x);
    int n4q = QKV_E * DD / 4;
    split_bf16<<<(n4q + 255) / 256, 256>>>(w_qkv, (__nv_bfloat16*)wqhi_p,
                                           (__nv_bfloat16*)wqlo_p, n4q);
    int n4w = DD * DD / 4;
    split_bf16<<<(n4w + 255) / 256, 256>>>(w_out, (__nv_bfloat16*)wohi_p,
                                           (__nv_bfloat16*)wolo_p, n4w);

    // 1) QKV projection -> split fp16 q/k/v (q pre-scaled), [b,h,s,64]
    dim3 g1(QKV_E / 128, MROWS / 128);
    gemm_mma<1><<<g1, 256, GM_SMEM>>>(
        (const __nv_bfloat16*)xhi_p, (const __nv_bfloat16*)xlo_p,
        (const __nv_bfloat16*)wqhi_p, (const __nv_bfloat16*)wqlo_p,
        nullptr, nullptr,
        (__half*)qh_p, (__half*)ql_p, (__half*)kh_p, (__half*)kl_p,
        (__half*)vh_p, (__half*)vl_p, MROWS, QKV_E, DD);

    // 2) tensor-core flash attention -> bf16 hi/lo o
    dim3 g2(SS / 128, BB * HH);
    flash_mma<<<g2, 256, FA_SMEM>>>(
        (const __half*)qh_p, (const __half*)ql_p,
        (const __half*)kh_p, (const __half*)kl_p,
        (const __half*)vh_p, (const __half*)vl_p,
        (__nv_bfloat16*)ohi_p, (__nv_bfloat16*)olo_p);

    // 3) output projection with bias -> fp32 out
    dim3 g3(DD / 128, MROWS / 128);
    gemm_mma<0><<<g3, 256, GM_SMEM>>>(
        (const __nv_bfloat16*)ohi_p, (const __nv_bfloat16*)olo_p,
        (const __nv_bfloat16*)wohi_p, (const __nv_bfloat16*)wolo_p,
        b_out, out,
        nullptr, nullptr, nullptr, nullptr, nullptr, nullptr,
        MROWS, DD, DD);
}

// round 5
// speedup vs baseline: 5.1054x; 1.3966x over previous
#include <cuda_runtime.h>
#include <cuda_fp16.h>

// Problem constants
#define BB   2
#define SS   2048
#define DD   1024
#define HH   16
#define HDIM 64
#define MROWS (BB * SS)           // 4096
#define QKV_E (3 * DD)            // 3072
#define SCALE 0.125f              // 1/sqrt(64)

// Scratch (device globals per harness allocation rules)
__device__ __align__(16) __half g_xhi[MROWS * DD];
__device__ __align__(16) __half g_xlo[MROWS * DD];
__device__ __align__(16) __half g_wqh[QKV_E * DD];
__device__ __align__(16) __half g_woh[DD * DD];
__device__ __align__(16) __half g_ohi[MROWS * DD];
__device__ __align__(16) __half g_olo[MROWS * DD];
// fp16 q (hi+lo, pre-scaled), k, v in [b][h][s][64] layout
#define QKVN (BB * HH * SS * HDIM)
__device__ __align__(16) __half g_qh[QKVN];
__device__ __align__(16) __half g_ql[QKVN];
__device__ __align__(16) __half g_kh[QKVN];
__device__ __align__(16) __half g_vh[QKVN];

__device__ __forceinline__ unsigned smem_u32(const void* p) {
    unsigned a;
    asm("{ .reg .u64 t; cvta.to.shared.u64 t, %1; cvt.u32.u64 %0, t; }"
        : "=r"(a) : "l"(p));
    return a;
}

// ---------------------------------------------------------------------------
// fp32 -> fp16 hi (+ optional lo residual)
// ---------------------------------------------------------------------------
__global__ __launch_bounds__(256) void split_fp16(
    const float* __restrict__ x, __half* __restrict__ hi,
    __half* __restrict__ lo, int n4)
{
    int i = blockIdx.x * blockDim.x + threadIdx.x;
    if (i >= n4) return;
    float4 v = *(const float4*)(x + i * 4);
    __half h0 = __float2half_rn(v.x);
    __half h1 = __float2half_rn(v.y);
    __half h2 = __float2half_rn(v.z);
    __half h3 = __float2half_rn(v.w);
    __half2 H0; H0.x = h0; H0.y = h1;
    __half2 H1; H1.x = h2; H1.y = h3;
    ((__half2*)hi)[i * 2 + 0] = H0;
    ((__half2*)hi)[i * 2 + 1] = H1;
    if (lo) {
        __half2 L0, L1;
        L0.x = __float2half_rn(v.x - __half2float(h0));
        L0.y = __float2half_rn(v.y - __half2float(h1));
        L1.x = __float2half_rn(v.z - __half2float(h2));
        L1.y = __float2half_rn(v.w - __half2float(h3));
        ((__half2*)lo)[i * 2 + 0] = L0;
        ((__half2*)lo)[i * 2 + 1] = L1;
    }
}

// ---------------------------------------------------------------------------
// MMA primitives
// ---------------------------------------------------------------------------
__device__ __forceinline__ void ldsm4(unsigned addr, unsigned& r0, unsigned& r1,
                                      unsigned& r2, unsigned& r3) {
    asm volatile("ldmatrix.sync.aligned.m8n8.x4.shared.b16 {%0,%1,%2,%3}, [%4];"
                 : "=r"(r0), "=r"(r1), "=r"(r2), "=r"(r3) : "r"(addr));
}
__device__ __forceinline__ void ldsm4t(unsigned addr, unsigned& r0, unsigned& r1,
                                       unsigned& r2, unsigned& r3) {
    asm volatile("ldmatrix.sync.aligned.m8n8.x4.trans.shared.b16 {%0,%1,%2,%3}, [%4];"
                 : "=r"(r0), "=r"(r1), "=r"(r2), "=r"(r3) : "r"(addr));
}
__device__ __forceinline__ void mma_fp(float* d, const unsigned* a,
                                       unsigned b0, unsigned b1) {
    asm volatile(
        "mma.sync.aligned.m16n8k16.row.col.f32.f16.f16.f32 "
        "{%0,%1,%2,%3}, {%4,%5,%6,%7}, {%8,%9}, {%0,%1,%2,%3};"
        : "+f"(d[0]), "+f"(d[1]), "+f"(d[2]), "+f"(d[3])
        : "r"(a[0]), "r"(a[1]), "r"(a[2]), "r"(a[3]), "r"(b0), "r"(b1));
}

// ---------------------------------------------------------------------------
// 2-pass exact-A x fp16(B) NT GEMM: C = (Ahi+Alo) @ Bhi^T (+bias).
// 128x128 block, KC=64, 256 thr, 3-stage cp.async.
// MODE 0: fp32 C.  MODE 1: QKV epilogue (q hi/lo scaled, k hi, v hi).
// ---------------------------------------------------------------------------
#define KC 64
#define STAGE_BYTES 49152          // Ahi 16K + Alo 16K + Bhi 16K
#define GM_SMEM (3 * STAGE_BYTES)  // 144KB

template <int MODE>
__global__ __launch_bounds__(256) void gemm2(
    const __half* __restrict__ Ahi, const __half* __restrict__ Alo,
    const __half* __restrict__ Bhi,
    const float* __restrict__ bias, float* __restrict__ C,
    __half* __restrict__ qh, __half* __restrict__ ql,
    __half* __restrict__ kh, __half* __restrict__ vh,
    int M, int N, int K)
{
    extern __shared__ __align__(1024) char sm[];
    const unsigned sb = smem_u32(sm);
    const int tid  = threadIdx.x;
    const int lane = tid & 31;
    const int wid  = tid >> 5;
    const int wm   = wid >> 2;
    const int wn   = wid & 3;
    const int m0   = blockIdx.y * 128;
    const int n0   = blockIdx.x * 128;

    const __half* src0 = Ahi + (size_t)m0 * K;
    const __half* src1 = Alo + (size_t)m0 * K;
    const __half* src2 = Bhi + (size_t)n0 * K;

    const int lr0  = tid >> 3;
    const int lc16 = tid & 7;

    float acc[4][4][4];
#pragma unroll
    for (int i = 0; i < 4; i++)
#pragma unroll
        for (int j = 0; j < 4; j++)
#pragma unroll
            for (int q = 0; q < 4; q++) acc[i][j][q] = 0.f;

    const int nch = K / KC;

    auto issue = [&](int cc, int stg) {
        const int k0 = cc * KC;
        const unsigned sbase = sb + stg * STAGE_BYTES;
        const __half* srcs[3] = {src0, src1, src2};
#pragma unroll
        for (int op = 0; op < 3; op++) {
            const __half* s = srcs[op];
            const unsigned dst = sbase + op * 16384;
#pragma unroll
            for (int it = 0; it < 4; it++) {
                int r = lr0 + it * 32;
                unsigned saddr = dst + r * 128 + ((lc16 * 16) ^ ((r & 7) << 4));
                const void* g = s + (size_t)r * K + k0 + lc16 * 8;
                asm volatile("cp.async.cg.shared.global [%0], [%1], 16;"
                             :: "r"(saddr), "l"(g));
            }
        }
        asm volatile("cp.async.commit_group;" ::: "memory");
    };

    issue(0, 0);
    if (nch > 1) issue(1, 1);

    const int arow = (lane & 15);
    const unsigned acb0 = (lane >> 4) * 16;
    const int bnr  = (lane & 7) + ((lane >> 4) << 3);
    const unsigned bcb0 = ((lane >> 3) & 1) * 16;

    for (int cc = 0; cc < nch; cc++) {
        if (cc + 2 < nch) {
            issue(cc + 2, (cc + 2) % 3);
            asm volatile("cp.async.wait_group 2;" ::: "memory");
        } else if (cc + 1 < nch) {
            asm volatile("cp.async.wait_group 1;" ::: "memory");
        } else {
            asm volatile("cp.async.wait_group 0;" ::: "memory");
        }
        __syncthreads();

        const unsigned sbase = sb + (cc % 3) * STAGE_BYTES;
        const unsigned Ah = sbase, Al = sbase + 16384, Bb = sbase + 32768;

#pragma unroll
        for (int k16 = 0; k16 < 4; k16++) {
            unsigned ah[4][4], al[4][4];
#pragma unroll
            for (int mt = 0; mt < 4; mt++) {
                int r = wm * 64 + mt * 16 + arow;
                unsigned cb = k16 * 32 + acb0;
                unsigned off = r * 128 + (cb ^ ((r & 7) << 4));
                ldsm4(Ah + off, ah[mt][0], ah[mt][1], ah[mt][2], ah[mt][3]);
                ldsm4(Al + off, al[mt][0], al[mt][1], al[mt][2], al[mt][3]);
            }
            unsigned b[2][4];
#pragma unroll
            for (int bt = 0; bt < 2; bt++) {
                int n = wn * 32 + bt * 16 + bnr;
                unsigned cb = k16 * 32 + bcb0;
                unsigned addr = Bb + n * 128 + (cb ^ ((n & 7) << 4));
                ldsm4(addr, b[bt][0], b[bt][1], b[bt][2], b[bt][3]);
            }
#pragma unroll
            for (int mt = 0; mt < 4; mt++)
#pragma unroll
                for (int nt = 0; nt < 4; nt++) {
                    unsigned b0 = b[nt >> 1][(nt & 1) * 2];
                    unsigned b1 = b[nt >> 1][(nt & 1) * 2 + 1];
                    mma_fp(acc[mt][nt], ah[mt], b0, b1);
                    mma_fp(acc[mt][nt], al[mt], b0, b1);
                }
        }
        __syncthreads();
    }

    // ---- epilogue ----
#pragma unroll
    for (int mt = 0; mt < 4; mt++) {
        int r0 = m0 + wm * 64 + mt * 16 + (lane >> 2);
#pragma unroll
        for (int nt = 0; nt < 4; nt++) {
            int c = n0 + wn * 32 + nt * 8 + (lane & 3) * 2;
            if (MODE == 0) {
                float2 bv = make_float2(0.f, 0.f);
                if (bias) bv = *(const float2*)(bias + c);
                *(float2*)(C + (size_t)r0 * N + c) =
                    make_float2(acc[mt][nt][0] + bv.x, acc[mt][nt][1] + bv.y);
                *(float2*)(C + (size_t)(r0 + 8) * N + c) =
                    make_float2(acc[mt][nt][2] + bv.x, acc[mt][nt][3] + bv.y);
            } else {
                int which = c >> 10;           // 0: v, 1: q, 2: k
                int rem   = c & 1023;
                int h     = rem >> 6;
                int d     = rem & 63;
#pragma unroll
                for (int half_ = 0; half_ < 2; half_++) {
                    int row = r0 + half_ * 8;
                    float v0 = acc[mt][nt][half_ * 2 + 0];
                    float v1 = acc[mt][nt][half_ * 2 + 1];
                    int b = row >> 11, s = row & 2047;
                    size_t idx = ((size_t)(b * HH + h) * SS + s) * HDIM + d;
                    if (which == 1) {
                        v0 *= SCALE; v1 *= SCALE;
                        __half h0 = __float2half_rn(v0);
                        __half h1 = __float2half_rn(v1);
                        __half2 Hp; Hp.x = h0; Hp.y = h1;
                        __half2 Lp;
                        Lp.x = __float2half_rn(v0 - __half2float(h0));
                        Lp.y = __float2half_rn(v1 - __half2float(h1));
                        *(__half2*)(qh + idx) = Hp;
                        *(__half2*)(ql + idx) = Lp;
                    } else {
                        __half2 Hp;
                        Hp.x = __float2half_rn(v0);
                        Hp.y = __float2half_rn(v1);
                        __half* dst = (which == 0) ? vh : kh;
                        *(__half2*)(dst + idx) = Hp;
                    }
                }
            }
        }
    }
}

// ---------------------------------------------------------------------------
// Tensor-core flash attention, 2-pass (exact-Q x Khi, exact-P x Vhi).
// Block: 128 q rows, 8 warps, BK=64, 3-stage cp.async KV.
// ---------------------------------------------------------------------------
#define FA_SMEM (32768 + 3 * 16384)   // Qhi/Qlo + 3 KV stages = 80KB

__global__ __launch_bounds__(256) void flash_mma(
    const __half* __restrict__ Qhi, const __half* __restrict__ Qlo,
    const __half* __restrict__ Khi, const __half* __restrict__ Vhi,
    __half* __restrict__ Ohi, __half* __restrict__ Olo)
{
    extern __shared__ __align__(1024) char sm[];
    const unsigned sb = smem_u32(sm);
    const int tid  = threadIdx.x;
    const int lane = tid & 31;
    const int wid  = tid >> 5;
    const int q0   = blockIdx.x * 128;
    const int bh   = blockIdx.y;

    const size_t base = (size_t)bh * SS * HDIM;
    const __half* qhg = Qhi + base;
    const __half* qlg = Qlo + base;
    const __half* khg = Khi + base;
    const __half* vhg = Vhi + base;

    const unsigned sQh = sb, sQl = sb + 16384;
    const unsigned sStage = sb + 32768;

    // ---- Q tiles (128 x 64 fp16, hi+lo) ----
#pragma unroll
    for (int it = 0; it < 4; it++) {
        int idx = it * 256 + tid;
        int r   = idx >> 3;
        int c16 = idx & 7;
        unsigned off = r * 128 + ((c16 * 16) ^ ((r & 7) << 4));
        const void* gh = qhg + (size_t)(q0 + r) * HDIM + c16 * 8;
        const void* gl = qlg + (size_t)(q0 + r) * HDIM + c16 * 8;
        asm volatile("cp.async.cg.shared.global [%0], [%1], 16;"
                     :: "r"(sQh + off), "l"(gh));
        asm volatile("cp.async.cg.shared.global [%0], [%1], 16;"
                     :: "r"(sQl + off), "l"(gl));
    }
    asm volatile("cp.async.commit_group;" ::: "memory");

    auto issue_kv = [&](int i, int stg) {
        const int kv0 = i * 64;
        const unsigned s0 = sStage + stg * 16384;
        const __half* srcs[2] = {khg, vhg};
#pragma unroll
        for (int op = 0; op < 2; op++) {
            const unsigned dst = s0 + op * 8192;
#pragma unroll
            for (int it = 0; it < 2; it++) {
                int idx = it * 256 + tid;
                int r   = idx >> 3;
                int c16 = idx & 7;
                unsigned saddr = dst + r * 128 + ((c16 * 16) ^ ((r & 7) << 4));
                const void* g = srcs[op] + (size_t)(kv0 + r) * HDIM + c16 * 8;
                asm volatile("cp.async.cg.shared.global [%0], [%1], 16;"
                             :: "r"(saddr), "l"(g));
            }
        }
        asm volatile("cp.async.commit_group;" ::: "memory");
    };

    issue_kv(0, 0);
    issue_kv(1, 1);
    asm volatile("cp.async.wait_group 2;" ::: "memory");   // Q done
    __syncthreads();

    // ---- persistent Q a-frags ----
    unsigned qhf[4][4], qlf[4][4];
    {
        const int arow = wid * 16 + (lane & 15);
        const unsigned acb0 = (lane >> 4) * 16;
#pragma unroll
        for (int ks = 0; ks < 4; ks++) {
            unsigned cb = ks * 32 + acb0;
            unsigned off = arow * 128 + (cb ^ ((arow & 7) << 4));
            ldsm4(sQh + off, qhf[ks][0], qhf[ks][1], qhf[ks][2], qhf[ks][3]);
            ldsm4(sQl + off, qlf[ks][0], qlf[ks][1], qlf[ks][2], qlf[ks][3]);
        }
    }

    float o[8][4];
#pragma unroll
    for (int i = 0; i < 8; i++)
#pragma unroll
        for (int j = 0; j < 4; j++) o[i][j] = 0.f;
    float m0r = -1e30f, m1r = -1e30f, l0r = 0.f, l1r = 0.f;

    const int bnr  = (lane & 7) + ((lane >> 4) << 3);
    const unsigned bcb0 = ((lane >> 3) & 1) * 16;
    const int vrow0 = (lane & 7) + (((lane >> 3) & 1) << 3);
    const unsigned vcb = (lane >> 4) * 16;

    const int NIT = SS / 64;   // 32
    for (int cc = 0; cc < NIT; cc++) {
        if (cc + 2 < NIT) {
            issue_kv(cc + 2, (cc + 2) % 3);
            asm volatile("cp.async.wait_group 2;" ::: "memory");
        } else if (cc + 1 < NIT) {
            asm volatile("cp.async.wait_group 1;" ::: "memory");
        } else {
            asm volatile("cp.async.wait_group 0;" ::: "memory");
        }
        __syncthreads();

        const unsigned st = sStage + (cc % 3) * 16384;
        const unsigned sKh = st, sVh = st + 8192;

        // ---- S = Q K^T (2-pass: Qhi + Qlo vs Khi) ----
        float s[8][4];
#pragma unroll
        for (int i = 0; i < 8; i++)
#pragma unroll
            for (int j = 0; j < 4; j++) s[i][j] = 0.f;

#pragma unroll
        for (int ks = 0; ks < 4; ks++) {
#pragma unroll
            for (int g = 0; g < 4; g++) {
                int r = g * 16 + bnr;
                unsigned cb = ks * 32 + bcb0;
                unsigned off = r * 128 + (cb ^ ((r & 7) << 4));
                unsigned h0, h1, h2, h3;
                ldsm4(sKh + off, h0, h1, h2, h3);
                mma_fp(s[2 * g],     qhf[ks], h0, h1);
                mma_fp(s[2 * g],     qlf[ks], h0, h1);
                mma_fp(s[2 * g + 1], qhf[ks], h2, h3);
                mma_fp(s[2 * g + 1], qlf[ks], h2, h3);
            }
        }

        // ---- online softmax (scale pre-applied to Q) ----
        float mx0 = -1e30f, mx1 = -1e30f;
#pragma unroll
        for (int nt = 0; nt < 8; nt++) {
            mx0 = fmaxf(mx0, fmaxf(s[nt][0], s[nt][1]));
            mx1 = fmaxf(mx1, fmaxf(s[nt][2], s[nt][3]));
        }
        mx0 = fmaxf(mx0, __shfl_xor_sync(0xffffffffu, mx0, 1));
        mx0 = fmaxf(mx0, __shfl_xor_sync(0xffffffffu, mx0, 2));
        mx1 = fmaxf(mx1, __shfl_xor_sync(0xffffffffu, mx1, 1));
        mx1 = fmaxf(mx1, __shfl_xor_sync(0xffffffffu, mx1, 2));
        float mn0 = fmaxf(m0r, mx0), mn1 = fmaxf(m1r, mx1);
        float f0 = __expf(m0r - mn0), f1 = __expf(m1r - mn1);
        float sum0 = 0.f, sum1 = 0.f;
#pragma unroll
        for (int nt = 0; nt < 8; nt++) {
            s[nt][0] = __expf(s[nt][0] - mn0);
            s[nt][1] = __expf(s[nt][1] - mn0);
            s[nt][2] = __expf(s[nt][2] - mn1);
            s[nt][3] = __expf(s[nt][3] - mn1);
            sum0 += s[nt][0] + s[nt][1];
            sum1 += s[nt][2] + s[nt][3];
        }
        sum0 += __shfl_xor_sync(0xffffffffu, sum0, 1);
        sum0 += __shfl_xor_sync(0xffffffffu, sum0, 2);
        sum1 += __shfl_xor_sync(0xffffffffu, sum1, 1);
        sum1 += __shfl_xor_sync(0xffffffffu, sum1, 2);
        l0r = l0r * f0 + sum0;
        l1r = l1r * f1 + sum1;
        m0r = mn0; m1r = mn1;
#pragma unroll
        for (int nd = 0; nd < 8; nd++) {
            o[nd][0] *= f0; o[nd][1] *= f0;
            o[nd][2] *= f1; o[nd][3] *= f1;
        }

        // ---- O += P V (2-pass: Phi + Plo vs Vhi) ----
#pragma unroll
        for (int kk = 0; kk < 4; kk++) {
            float2 p00 = make_float2(s[2 * kk][0], s[2 * kk][1]);
            float2 p01 = make_float2(s[2 * kk][2], s[2 * kk][3]);
            float2 p10 = make_float2(s[2 * kk + 1][0], s[2 * kk + 1][1]);
            float2 p11 = make_float2(s[2 * kk + 1][2], s[2 * kk + 1][3]);
            __half2 H0 = __float22half2_rn(p00);
            __half2 H1 = __float22half2_rn(p01);
            __half2 H2 = __float22half2_rn(p10);
            __half2 H3 = __float22half2_rn(p11);
            float2 r0 = __half22float2(H0), r1 = __half22float2(H1);
            float2 r2 = __half22float2(H2), r3 = __half22float2(H3);
            __half2 L0 = __float22half2_rn(make_float2(p00.x - r0.x, p00.y - r0.y));
            __half2 L1 = __float22half2_rn(make_float2(p01.x - r1.x, p01.y - r1.y));
            __half2 L2 = __float22half2_rn(make_float2(p10.x - r2.x, p10.y - r2.y));
            __half2 L3 = __float22half2_rn(make_float2(p11.x - r3.x, p11.y - r3.y));
            unsigned pah[4] = {*(unsigned*)&H0, *(unsigned*)&H1,
                               *(unsigned*)&H2, *(unsigned*)&H3};
            unsigned pal[4] = {*(unsigned*)&L0, *(unsigned*)&L1,
                               *(unsigned*)&L2, *(unsigned*)&L3};

#pragma unroll
            for (int np = 0; np < 4; np++) {
                int r = kk * 16 + vrow0;
                unsigned cb = (np * 2) * 16 + vcb;
                unsigned off = r * 128 + (cb ^ ((r & 7) << 4));
                unsigned v0, v1, v2, v3;
                ldsm4t(sVh + off, v0, v1, v2, v3);
                mma_fp(o[2 * np],     pah, v0, v1);
                mma_fp(o[2 * np],     pal, v0, v1);
                mma_fp(o[2 * np + 1], pah, v2, v3);
                mma_fp(o[2 * np + 1], pal, v2, v3);
            }
        }
        __syncthreads();
    }

    // ---- epilogue: normalize + write fp16 hi/lo [4096][1024] ----
    const float inv0 = 1.f / l0r, inv1 = 1.f / l1r;
    const int b = bh >> 4, h = bh & 15;
    const int row0 = q0 + wid * 16 + (lane >> 2);
    const int grow0 = b * SS + row0;
    const int col0 = h * HDIM + (lane & 3) * 2;
#pragma unroll
    for (int nd = 0; nd < 8; nd++) {
        int c = col0 + nd * 8;
#pragma unroll
        for (int half_ = 0; half_ < 2; half_++) {
            float v0 = o[nd][half_ * 2 + 0] * (half_ ? inv1 : inv0);
            float v1 = o[nd][half_ * 2 + 1] * (half_ ? inv1 : inv0);
            size_t idx = (size_t)(grow0 + half_ * 8) * DD + c;
            __half h0 = __float2half_rn(v0);
            __half h1 = __float2half_rn(v1);
            __half2 Hp; Hp.x = h0; Hp.y = h1;
            __half2 Lp;
            Lp.x = __float2half_rn(v0 - __half2float(h0));
            Lp.y = __float2half_rn(v1 - __half2float(h1));
            *(__half2*)(Ohi + idx) = Hp;
            *(__half2*)(Olo + idx) = Lp;
        }
    }
}

// ---------------------------------------------------------------------------
extern "C" void kernel_launch(void* const* d_in, const int* in_sizes, int n_in,
                              void* d_out, int out_size)
{
    const float* x     = (const float*)d_in[0];
    const float* w_qkv = (const float*)d_in[1];
    const float* w_out = (const float*)d_in[2];
    const float* b_out = (const float*)d_in[3];
    float* out = (float*)d_out;

    void *xhi_p, *xlo_p, *wqh_p, *woh_p, *ohi_p, *olo_p;
    void *qh_p, *ql_p, *kh_p, *vh_p;
    cudaGetSymbolAddress(&xhi_p, g_xhi);
    cudaGetSymbolAddress(&xlo_p, g_xlo);
    cudaGetSymbolAddress(&wqh_p, g_wqh);
    cudaGetSymbolAddress(&woh_p, g_woh);
    cudaGetSymbolAddress(&ohi_p, g_ohi);
    cudaGetSymbolAddress(&olo_p, g_olo);
    cudaGetSymbolAddress(&qh_p, g_qh);
    cudaGetSymbolAddress(&ql_p, g_ql);
    cudaGetSymbolAddress(&kh_p, g_kh);
    cudaGetSymbolAddress(&vh_p, g_vh);

    cudaFuncSetAttribute(gemm2<0>,
                         cudaFuncAttributeMaxDynamicSharedMemorySize, GM_SMEM);
    cudaFuncSetAttribute(gemm2<1>,
                         cudaFuncAttributeMaxDynamicSharedMemorySize, GM_SMEM);
    cudaFuncSetAttribute(flash_mma,
                         cudaFuncAttributeMaxDynamicSharedMemorySize, FA_SMEM);

    // 0) splits: x -> fp16 hi+lo; weights -> fp16 hi only
    int n4x = MROWS * DD / 4;
    split_fp16<<<(n4x + 255) / 256, 256>>>(x, (__half*)xhi_p, (__half*)xlo_p, n4x);
    int n4q = QKV_E * DD / 4;
    split_fp16<<<(n4q + 255) / 256, 256>>>(w_qkv, (__half*)wqh_p, nullptr, n4q);
    int n4w = DD * DD / 4;
    split_fp16<<<(n4w + 255) / 256, 256>>>(w_out, (__half*)woh_p, nullptr, n4w);

    // 1) QKV projection -> q hi/lo (pre-scaled), k hi, v hi in [b,h,s,64]
    dim3 g1(QKV_E / 128, MROWS / 128);
    gemm2<1><<<g1, 256, GM_SMEM>>>(
        (const __half*)xhi_p, (const __half*)xlo_p, (const __half*)wqh_p,
        nullptr, nullptr,
        (__half*)qh_p, (__half*)ql_p, (__half*)kh_p, (__half*)vh_p,
        MROWS, QKV_E, DD);

    // 2) flash attention -> o fp16 hi/lo
    dim3 g2(SS / 128, BB * HH);
    flash_mma<<<g2, 256, FA_SMEM>>>(
        (const __half*)qh_p, (const __half*)ql_p,
        (const __half*)kh_p, (const __half*)vh_p,
        (__half*)ohi_p, (__half*)olo_p);

    // 3) output projection with bias -> fp32 out
    dim3 g3(DD / 128, MROWS / 128);
    gemm2<0><<<g3, 256, GM_SMEM>>>(
        (const __half*)ohi_p, (const __half*)olo_p, (const __half*)woh_p,
        b_out, out,
        nullptr, nullptr, nullptr, nullptr,
        MROWS, DD, DD);
}

// round 6
// speedup vs baseline: 5.5478x; 1.0867x over previous
#include <cuda_runtime.h>
#include <cuda_fp16.h>

// Problem constants
#define BB   2
#define SS   2048
#define DD   1024
#define HH   16
#define HDIM 64
#define MROWS (BB * SS)           // 4096
#define QKV_E (3 * DD)            // 3072
#define SCALE 0.125f              // 1/sqrt(64)

// Scratch (device globals per harness allocation rules)
__device__ __align__(16) __half g_xhi[MROWS * DD];
__device__ __align__(16) __half g_xlo[MROWS * DD];
__device__ __align__(16) __half g_wqh[QKV_E * DD];
__device__ __align__(16) __half g_woh[DD * DD];
__device__ __align__(16) __half g_ohi[MROWS * DD];
__device__ __align__(16) __half g_olo[MROWS * DD];
#define QKVN (BB * HH * SS * HDIM)
__device__ __align__(16) __half g_qh[QKVN];
__device__ __align__(16) __half g_ql[QKVN];
__device__ __align__(16) __half g_kh[QKVN];
__device__ __align__(16) __half g_vh[QKVN];

__device__ __forceinline__ unsigned smem_u32(const void* p) {
    unsigned a;
    asm("{ .reg .u64 t; cvta.to.shared.u64 t, %1; cvt.u32.u64 %0, t; }"
        : "=r"(a) : "l"(p));
    return a;
}

// ---------------------------------------------------------------------------
// fp32 -> fp16 hi (+ optional lo residual)
// ---------------------------------------------------------------------------
__global__ __launch_bounds__(256) void split_fp16(
    const float* __restrict__ x, __half* __restrict__ hi,
    __half* __restrict__ lo, int n4)
{
    int i = blockIdx.x * blockDim.x + threadIdx.x;
    if (i >= n4) return;
    float4 v = *(const float4*)(x + i * 4);
    __half h0 = __float2half_rn(v.x);
    __half h1 = __float2half_rn(v.y);
    __half h2 = __float2half_rn(v.z);
    __half h3 = __float2half_rn(v.w);
    __half2 H0; H0.x = h0; H0.y = h1;
    __half2 H1; H1.x = h2; H1.y = h3;
    ((__half2*)hi)[i * 2 + 0] = H0;
    ((__half2*)hi)[i * 2 + 1] = H1;
    if (lo) {
        __half2 L0, L1;
        L0.x = __float2half_rn(v.x - __half2float(h0));
        L0.y = __float2half_rn(v.y - __half2float(h1));
        L1.x = __float2half_rn(v.z - __half2float(h2));
        L1.y = __float2half_rn(v.w - __half2float(h3));
        ((__half2*)lo)[i * 2 + 0] = L0;
        ((__half2*)lo)[i * 2 + 1] = L1;
    }
}

// ---------------------------------------------------------------------------
// MMA primitives
// ---------------------------------------------------------------------------
__device__ __forceinline__ void ldsm4(unsigned addr, unsigned& r0, unsigned& r1,
                                      unsigned& r2, unsigned& r3) {
    asm volatile("ldmatrix.sync.aligned.m8n8.x4.shared.b16 {%0,%1,%2,%3}, [%4];"
                 : "=r"(r0), "=r"(r1), "=r"(r2), "=r"(r3) : "r"(addr));
}
__device__ __forceinline__ void ldsm4t(unsigned addr, unsigned& r0, unsigned& r1,
                                       unsigned& r2, unsigned& r3) {
    asm volatile("ldmatrix.sync.aligned.m8n8.x4.trans.shared.b16 {%0,%1,%2,%3}, [%4];"
                 : "=r"(r0), "=r"(r1), "=r"(r2), "=r"(r3) : "r"(addr));
}
__device__ __forceinline__ void mma_fp(float* d, const unsigned* a,
                                       unsigned b0, unsigned b1) {
    asm volatile(
        "mma.sync.aligned.m16n8k16.row.col.f32.f16.f16.f32 "
        "{%0,%1,%2,%3}, {%4,%5,%6,%7}, {%8,%9}, {%0,%1,%2,%3};"
        : "+f"(d[0]), "+f"(d[1]), "+f"(d[2]), "+f"(d[3])
        : "r"(a[0]), "r"(a[1]), "r"(a[2]), "r"(a[3]), "r"(b0), "r"(b1));
}

// ---------------------------------------------------------------------------
// 2-pass exact-A x fp16(B) NT GEMM: C = (Ahi+Alo) @ Bhi^T (+bias).
// 128x128 block, KC=64, 256 thr, 2-stage cp.async, 2 CTAs/SM.
// MODE 0: fp32 C.  MODE 1: QKV epilogue.
// ---------------------------------------------------------------------------
#define KC 64
#define STAGE_BYTES 49152          // Ahi 16K + Alo 16K + Bhi 16K
#define GM_SMEM (2 * STAGE_BYTES)  // 96KB -> 2 CTAs/SM

template <int MODE>
__global__ __launch_bounds__(256, 2) void gemm2(
    const __half* __restrict__ Ahi, const __half* __restrict__ Alo,
    const __half* __restrict__ Bhi,
    const float* __restrict__ bias, float* __restrict__ C,
    __half* __restrict__ qh, __half* __restrict__ ql,
    __half* __restrict__ kh, __half* __restrict__ vh,
    int M, int N, int K)
{
    extern __shared__ __align__(1024) char sm[];
    const unsigned sb = smem_u32(sm);
    const int tid  = threadIdx.x;
    const int lane = tid & 31;
    const int wid  = tid >> 5;
    const int wm   = wid >> 2;
    const int wn   = wid & 3;
    const int m0   = blockIdx.y * 128;
    const int n0   = blockIdx.x * 128;

    const __half* src0 = Ahi + (size_t)m0 * K;
    const __half* src1 = Alo + (size_t)m0 * K;
    const __half* src2 = Bhi + (size_t)n0 * K;

    const int lr0  = tid >> 3;
    const int lc16 = tid & 7;

    float acc[4][4][4];
#pragma unroll
    for (int i = 0; i < 4; i++)
#pragma unroll
        for (int j = 0; j < 4; j++)
#pragma unroll
            for (int q = 0; q < 4; q++) acc[i][j][q] = 0.f;

    const int nch = K / KC;

    auto issue = [&](int cc, int stg) {
        const int k0 = cc * KC;
        const unsigned sbase = sb + stg * STAGE_BYTES;
        const __half* srcs[3] = {src0, src1, src2};
#pragma unroll
        for (int op = 0; op < 3; op++) {
            const __half* s = srcs[op];
            const unsigned dst = sbase + op * 16384;
#pragma unroll
            for (int it = 0; it < 4; it++) {
                int r = lr0 + it * 32;
                unsigned saddr = dst + r * 128 + ((lc16 * 16) ^ ((r & 7) << 4));
                const void* g = s + (size_t)r * K + k0 + lc16 * 8;
                asm volatile("cp.async.cg.shared.global [%0], [%1], 16;"
                             :: "r"(saddr), "l"(g));
            }
        }
        asm volatile("cp.async.commit_group;" ::: "memory");
    };

    issue(0, 0);

    const int arow = (lane & 15);
    const unsigned acb0 = (lane >> 4) * 16;
    const int bnr  = (lane & 7) + ((lane >> 4) << 3);
    const unsigned bcb0 = ((lane >> 3) & 1) * 16;

    for (int cc = 0; cc < nch; cc++) {
        if (cc + 1 < nch) {
            issue(cc + 1, (cc + 1) & 1);
            asm volatile("cp.async.wait_group 1;" ::: "memory");
        } else {
            asm volatile("cp.async.wait_group 0;" ::: "memory");
        }
        __syncthreads();

        const unsigned sbase = sb + (cc & 1) * STAGE_BYTES;
        const unsigned Ah = sbase, Al = sbase + 16384, Bb = sbase + 32768;

#pragma unroll
        for (int k16 = 0; k16 < 4; k16++) {
            unsigned ah[4][4], al[4][4];
#pragma unroll
            for (int mt = 0; mt < 4; mt++) {
                int r = wm * 64 + mt * 16 + arow;
                unsigned cb = k16 * 32 + acb0;
                unsigned off = r * 128 + (cb ^ ((r & 7) << 4));
                ldsm4(Ah + off, ah[mt][0], ah[mt][1], ah[mt][2], ah[mt][3]);
                ldsm4(Al + off, al[mt][0], al[mt][1], al[mt][2], al[mt][3]);
            }
            unsigned b[2][4];
#pragma unroll
            for (int bt = 0; bt < 2; bt++) {
                int n = wn * 32 + bt * 16 + bnr;
                unsigned cb = k16 * 32 + bcb0;
                unsigned addr = Bb + n * 128 + (cb ^ ((n & 7) << 4));
                ldsm4(addr, b[bt][0], b[bt][1], b[bt][2], b[bt][3]);
            }
            // hi sweep (16 independent MMAs), then lo sweep — no
            // back-to-back RAW on the same accumulator quad.
#pragma unroll
            for (int mt = 0; mt < 4; mt++)
#pragma unroll
                for (int nt = 0; nt < 4; nt++)
                    mma_fp(acc[mt][nt], ah[mt],
                           b[nt >> 1][(nt & 1) * 2],
                           b[nt >> 1][(nt & 1) * 2 + 1]);
#pragma unroll
            for (int mt = 0; mt < 4; mt++)
#pragma unroll
                for (int nt = 0; nt < 4; nt++)
                    mma_fp(acc[mt][nt], al[mt],
                           b[nt >> 1][(nt & 1) * 2],
                           b[nt >> 1][(nt & 1) * 2 + 1]);
        }
        __syncthreads();
    }

    // ---- epilogue ----
#pragma unroll
    for (int mt = 0; mt < 4; mt++) {
        int r0 = m0 + wm * 64 + mt * 16 + (lane >> 2);
#pragma unroll
        for (int nt = 0; nt < 4; nt++) {
            int c = n0 + wn * 32 + nt * 8 + (lane & 3) * 2;
            if (MODE == 0) {
                float2 bv = make_float2(0.f, 0.f);
                if (bias) bv = *(const float2*)(bias + c);
                *(float2*)(C + (size_t)r0 * N + c) =
                    make_float2(acc[mt][nt][0] + bv.x, acc[mt][nt][1] + bv.y);
                *(float2*)(C + (size_t)(r0 + 8) * N + c) =
                    make_float2(acc[mt][nt][2] + bv.x, acc[mt][nt][3] + bv.y);
            } else {
                int which = c >> 10;           // 0: v, 1: q, 2: k
                int rem   = c & 1023;
                int h     = rem >> 6;
                int d     = rem & 63;
#pragma unroll
                for (int half_ = 0; half_ < 2; half_++) {
                    int row = r0 + half_ * 8;
                    float v0 = acc[mt][nt][half_ * 2 + 0];
                    float v1 = acc[mt][nt][half_ * 2 + 1];
                    int b = row >> 11, s = row & 2047;
                    size_t idx = ((size_t)(b * HH + h) * SS + s) * HDIM + d;
                    if (which == 1) {
                        v0 *= SCALE; v1 *= SCALE;
                        __half h0 = __float2half_rn(v0);
                        __half h1 = __float2half_rn(v1);
                        __half2 Hp; Hp.x = h0; Hp.y = h1;
                        __half2 Lp;
                        Lp.x = __float2half_rn(v0 - __half2float(h0));
                        Lp.y = __float2half_rn(v1 - __half2float(h1));
                        *(__half2*)(qh + idx) = Hp;
                        *(__half2*)(ql + idx) = Lp;
                    } else {
                        __half2 Hp;
                        Hp.x = __float2half_rn(v0);
                        Hp.y = __float2half_rn(v1);
                        __half* dst = (which == 0) ? vh : kh;
                        *(__half2*)(dst + idx) = Hp;
                    }
                }
            }
        }
    }
}

// ---------------------------------------------------------------------------
// Tensor-core flash attention, 2-pass. 128 q rows/block, 8 warps, BK=64,
// 2-stage cp.async KV, 2 CTAs/SM.
// ---------------------------------------------------------------------------
#define FA_SMEM (32768 + 2 * 16384)   // Qhi/Qlo + 2 KV stages = 64KB

__global__ __launch_bounds__(256, 2) void flash_mma(
    const __half* __restrict__ Qhi, const __half* __restrict__ Qlo,
    const __half* __restrict__ Khi, const __half* __restrict__ Vhi,
    __half* __restrict__ Ohi, __half* __restrict__ Olo)
{
    extern __shared__ __align__(1024) char sm[];
    const unsigned sb = smem_u32(sm);
    const int tid  = threadIdx.x;
    const int lane = tid & 31;
    const int wid  = tid >> 5;
    const int q0   = blockIdx.x * 128;
    const int bh   = blockIdx.y;

    const size_t base = (size_t)bh * SS * HDIM;
    const __half* qhg = Qhi + base;
    const __half* qlg = Qlo + base;
    const __half* khg = Khi + base;
    const __half* vhg = Vhi + base;

    const unsigned sQh = sb, sQl = sb + 16384;
    const unsigned sStage = sb + 32768;

    // ---- Q tiles (128 x 64 fp16, hi+lo) ----
#pragma unroll
    for (int it = 0; it < 4; it++) {
        int idx = it * 256 + tid;
        int r   = idx >> 3;
        int c16 = idx & 7;
        unsigned off = r * 128 + ((c16 * 16) ^ ((r & 7) << 4));
        const void* gh = qhg + (size_t)(q0 + r) * HDIM + c16 * 8;
        const void* gl = qlg + (size_t)(q0 + r) * HDIM + c16 * 8;
        asm volatile("cp.async.cg.shared.global [%0], [%1], 16;"
                     :: "r"(sQh + off), "l"(gh));
        asm volatile("cp.async.cg.shared.global [%0], [%1], 16;"
                     :: "r"(sQl + off), "l"(gl));
    }
    asm volatile("cp.async.commit_group;" ::: "memory");

    auto issue_kv = [&](int i, int stg) {
        const int kv0 = i * 64;
        const unsigned s0 = sStage + stg * 16384;
        const __half* srcs[2] = {khg, vhg};
#pragma unroll
        for (int op = 0; op < 2; op++) {
            const unsigned dst = s0 + op * 8192;
#pragma unroll
            for (int it = 0; it < 2; it++) {
                int idx = it * 256 + tid;
                int r   = idx >> 3;
                int c16 = idx & 7;
                unsigned saddr = dst + r * 128 + ((c16 * 16) ^ ((r & 7) << 4));
                const void* g = srcs[op] + (size_t)(kv0 + r) * HDIM + c16 * 8;
                asm volatile("cp.async.cg.shared.global [%0], [%1], 16;"
                             :: "r"(saddr), "l"(g));
            }
        }
        asm volatile("cp.async.commit_group;" ::: "memory");
    };

    issue_kv(0, 0);
    asm volatile("cp.async.wait_group 1;" ::: "memory");   // Q done
    __syncthreads();

    // ---- persistent Q a-frags ----
    unsigned qhf[4][4], qlf[4][4];
    {
        const int arow = wid * 16 + (lane & 15);
        const unsigned acb0 = (lane >> 4) * 16;
#pragma unroll
        for (int ks = 0; ks < 4; ks++) {
            unsigned cb = ks * 32 + acb0;
            unsigned off = arow * 128 + (cb ^ ((arow & 7) << 4));
            ldsm4(sQh + off, qhf[ks][0], qhf[ks][1], qhf[ks][2], qhf[ks][3]);
            ldsm4(sQl + off, qlf[ks][0], qlf[ks][1], qlf[ks][2], qlf[ks][3]);
        }
    }

    float o[8][4];
#pragma unroll
    for (int i = 0; i < 8; i++)
#pragma unroll
        for (int j = 0; j < 4; j++) o[i][j] = 0.f;
    float m0r = -1e30f, m1r = -1e30f, l0r = 0.f, l1r = 0.f;

    const int bnr  = (lane & 7) + ((lane >> 4) << 3);
    const unsigned bcb0 = ((lane >> 3) & 1) * 16;
    const int vrow0 = (lane & 7) + (((lane >> 3) & 1) << 3);
    const unsigned vcb = (lane >> 4) * 16;

    const int NIT = SS / 64;   // 32
    for (int cc = 0; cc < NIT; cc++) {
        if (cc + 1 < NIT) {
            issue_kv(cc + 1, (cc + 1) & 1);
            asm volatile("cp.async.wait_group 1;" ::: "memory");
        } else {
            asm volatile("cp.async.wait_group 0;" ::: "memory");
        }
        __syncthreads();

        const unsigned st = sStage + (cc & 1) * 16384;
        const unsigned sKh = st, sVh = st + 8192;

        // ---- S = Q K^T (2-pass: Qhi + Qlo vs Khi) ----
        float s[8][4];
#pragma unroll
        for (int i = 0; i < 8; i++)
#pragma unroll
            for (int j = 0; j < 4; j++) s[i][j] = 0.f;

#pragma unroll
        for (int ks = 0; ks < 4; ks++) {
#pragma unroll
            for (int g = 0; g < 4; g++) {
                int r = g * 16 + bnr;
                unsigned cb = ks * 32 + bcb0;
                unsigned off = r * 128 + (cb ^ ((r & 7) << 4));
                unsigned h0, h1, h2, h3;
                ldsm4(sKh + off, h0, h1, h2, h3);
                // alternate accumulators to break RAW chains
                mma_fp(s[2 * g],     qhf[ks], h0, h1);
                mma_fp(s[2 * g + 1], qhf[ks], h2, h3);
                mma_fp(s[2 * g],     qlf[ks], h0, h1);
                mma_fp(s[2 * g + 1], qlf[ks], h2, h3);
            }
        }

        // ---- online softmax (scale pre-applied to Q) ----
        float mx0 = -1e30f, mx1 = -1e30f;
#pragma unroll
        for (int nt = 0; nt < 8; nt++) {
            mx0 = fmaxf(mx0, fmaxf(s[nt][0], s[nt][1]));
            mx1 = fmaxf(mx1, fmaxf(s[nt][2], s[nt][3]));
        }
        mx0 = fmaxf(mx0, __shfl_xor_sync(0xffffffffu, mx0, 1));
        mx0 = fmaxf(mx0, __shfl_xor_sync(0xffffffffu, mx0, 2));
        mx1 = fmaxf(mx1, __shfl_xor_sync(0xffffffffu, mx1, 1));
        mx1 = fmaxf(mx1, __shfl_xor_sync(0xffffffffu, mx1, 2));
        float mn0 = fmaxf(m0r, mx0), mn1 = fmaxf(m1r, mx1);
        float f0 = __expf(m0r - mn0), f1 = __expf(m1r - mn1);
        float sum0 = 0.f, sum1 = 0.f;
#pragma unroll
        for (int nt = 0; nt < 8; nt++) {
            s[nt][0] = __expf(s[nt][0] - mn0);
            s[nt][1] = __expf(s[nt][1] - mn0);
            s[nt][2] = __expf(s[nt][2] - mn1);
            s[nt][3] = __expf(s[nt][3] - mn1);
            sum0 += s[nt][0] + s[nt][1];
            sum1 += s[nt][2] + s[nt][3];
        }
        sum0 += __shfl_xor_sync(0xffffffffu, sum0, 1);
        sum0 += __shfl_xor_sync(0xffffffffu, sum0, 2);
        sum1 += __shfl_xor_sync(0xffffffffu, sum1, 1);
        sum1 += __shfl_xor_sync(0xffffffffu, sum1, 2);
        l0r = l0r * f0 + sum0;
        l1r = l1r * f1 + sum1;
        m0r = mn0; m1r = mn1;
#pragma unroll
        for (int nd = 0; nd < 8; nd++) {
            o[nd][0] *= f0; o[nd][1] *= f0;
            o[nd][2] *= f1; o[nd][3] *= f1;
        }

        // ---- O += P V (2-pass: Phi + Plo vs Vhi) ----
#pragma unroll
        for (int kk = 0; kk < 4; kk++) {
            float2 p00 = make_float2(s[2 * kk][0], s[2 * kk][1]);
            float2 p01 = make_float2(s[2 * kk][2], s[2 * kk][3]);
            float2 p10 = make_float2(s[2 * kk + 1][0], s[2 * kk + 1][1]);
            float2 p11 = make_float2(s[2 * kk + 1][2], s[2 * kk + 1][3]);
            __half2 H0 = __float22half2_rn(p00);
            __half2 H1 = __float22half2_rn(p01);
            __half2 H2 = __float22half2_rn(p10);
            __half2 H3 = __float22half2_rn(p11);
            float2 r0 = __half22float2(H0), r1 = __half22float2(H1);
            float2 r2 = __half22float2(H2), r3 = __half22float2(H3);
            __half2 L0 = __float22half2_rn(make_float2(p00.x - r0.x, p00.y - r0.y));
            __half2 L1 = __float22half2_rn(make_float2(p01.x - r1.x, p01.y - r1.y));
            __half2 L2 = __float22half2_rn(make_float2(p10.x - r2.x, p10.y - r2.y));
            __half2 L3 = __float22half2_rn(make_float2(p11.x - r3.x, p11.y - r3.y));
            unsigned pah[4] = {*(unsigned*)&H0, *(unsigned*)&H1,
                               *(unsigned*)&H2, *(unsigned*)&H3};
            unsigned pal[4] = {*(unsigned*)&L0, *(unsigned*)&L1,
                               *(unsigned*)&L2, *(unsigned*)&L3};

#pragma unroll
            for (int np = 0; np < 4; np++) {
                int r = kk * 16 + vrow0;
                unsigned cb = (np * 2) * 16 + vcb;
                unsigned off = r * 128 + (cb ^ ((r & 7) << 4));
                unsigned v0, v1, v2, v3;
                ldsm4t(sVh + off, v0, v1, v2, v3);
                // alternate accumulators
                mma_fp(o[2 * np],     pah, v0, v1);
                mma_fp(o[2 * np + 1], pah, v2, v3);
                mma_fp(o[2 * np],     pal, v0, v1);
                mma_fp(o[2 * np + 1], pal, v2, v3);
            }
        }
        __syncthreads();
    }

    // ---- epilogue: normalize + write fp16 hi/lo [4096][1024] ----
    const float inv0 = 1.f / l0r, inv1 = 1.f / l1r;
    const int b = bh >> 4, h = bh & 15;
    const int row0 = q0 + wid * 16 + (lane >> 2);
    const int grow0 = b * SS + row0;
    const int col0 = h * HDIM + (lane & 3) * 2;
#pragma unroll
    for (int nd = 0; nd < 8; nd++) {
        int c = col0 + nd * 8;
#pragma unroll
        for (int half_ = 0; half_ < 2; half_++) {
            float v0 = o[nd][half_ * 2 + 0] * (half_ ? inv1 : inv0);
            float v1 = o[nd][half_ * 2 + 1] * (half_ ? inv1 : inv0);
            size_t idx = (size_t)(grow0 + half_ * 8) * DD + c;
            __half h0 = __float2half_rn(v0);
            __half h1 = __float2half_rn(v1);
            __half2 Hp; Hp.x = h0; Hp.y = h1;
            __half2 Lp;
            Lp.x = __float2half_rn(v0 - __half2float(h0));
            Lp.y = __float2half_rn(v1 - __half2float(h1));
            *(__half2*)(Ohi + idx) = Hp;
            *(__half2*)(Olo + idx) = Lp;
        }
    }
}

// ---------------------------------------------------------------------------
extern "C" void kernel_launch(void* const* d_in, const int* in_sizes, int n_in,
                              void* d_out, int out_size)
{
    const float* x     = (const float*)d_in[0];
    const float* w_qkv = (const float*)d_in[1];
    const float* w_out = (const float*)d_in[2];
    const float* b_out = (const float*)d_in[3];
    float* out = (float*)d_out;

    void *xhi_p, *xlo_p, *wqh_p, *woh_p, *ohi_p, *olo_p;
    void *qh_p, *ql_p, *kh_p, *vh_p;
    cudaGetSymbolAddress(&xhi_p, g_xhi);
    cudaGetSymbolAddress(&xlo_p, g_xlo);
    cudaGetSymbolAddress(&wqh_p, g_wqh);
    cudaGetSymbolAddress(&woh_p, g_woh);
    cudaGetSymbolAddress(&ohi_p, g_ohi);
    cudaGetSymbolAddress(&olo_p, g_olo);
    cudaGetSymbolAddress(&qh_p, g_qh);
    cudaGetSymbolAddress(&ql_p, g_ql);
    cudaGetSymbolAddress(&kh_p, g_kh);
    cudaGetSymbolAddress(&vh_p, g_vh);

    cudaFuncSetAttribute(gemm2<0>,
                         cudaFuncAttributeMaxDynamicSharedMemorySize, GM_SMEM);
    cudaFuncSetAttribute(gemm2<1>,
                         cudaFuncAttributeMaxDynamicSharedMemorySize, GM_SMEM);
    cudaFuncSetAttribute(flash_mma,
                         cudaFuncAttributeMaxDynamicSharedMemorySize, FA_SMEM);

    // 0) splits: x -> fp16 hi+lo; weights -> fp16 hi only
    int n4x = MROWS * DD / 4;
    split_fp16<<<(n4x + 255) / 256, 256>>>(x, (__half*)xhi_p, (__half*)xlo_p, n4x);
    int n4q = QKV_E * DD / 4;
    split_fp16<<<(n4q + 255) / 256, 256>>>(w_qkv, (__half*)wqh_p, nullptr, n4q);
    int n4w = DD * DD / 4;
    split_fp16<<<(n4w + 255) / 256, 256>>>(w_out, (__half*)woh_p, nullptr, n4w);

    // 1) QKV projection -> q hi/lo (pre-scaled), k hi, v hi in [b,h,s,64]
    dim3 g1(QKV_E / 128, MROWS / 128);
    gemm2<1><<<g1, 256, GM_SMEM>>>(
        (const __half*)xhi_p, (const __half*)xlo_p, (const __half*)wqh_p,
        nullptr, nullptr,
        (__half*)qh_p, (__half*)ql_p, (__half*)kh_p, (__half*)vh_p,
        MROWS, QKV_E, DD);

    // 2) flash attention -> o fp16 hi/lo
    dim3 g2(SS / 128, BB * HH);
    flash_mma<<<g2, 256, FA_SMEM>>>(
        (const __half*)qh_p, (const __half*)ql_p,
        (const __half*)kh_p, (const __half*)vh_p,
        (__half*)ohi_p, (__half*)olo_p);

    // 3) output projection with bias -> fp32 out
    dim3 g3(DD / 128, MROWS / 128);
    gemm2<0><<<g3, 256, GM_SMEM>>>(
        (const __half*)ohi_p, (const __half*)olo_p, (const __half*)woh_p,
        b_out, out,
        nullptr, nullptr, nullptr, nullptr,
        MROWS, DD, DD);
}

// round 7
// speedup vs baseline: 5.8121x; 1.0477x over previous
#include <cuda_runtime.h>
#include <cuda_fp16.h>

// Problem constants
#define BB   2
#define SS   2048
#define DD   1024
#define HH   16
#define HDIM 64
#define MROWS (BB * SS)           // 4096
#define QKV_E (3 * DD)            // 3072
#define SCALE 0.125f              // 1/sqrt(64)
#define QSC   (0.125f * 1.4426950408889634f)   // SCALE * log2(e)

// Scratch (device globals per harness allocation rules)
__device__ __align__(16) __half g_xhi[MROWS * DD];
__device__ __align__(16) __half g_xlo[MROWS * DD];
__device__ __align__(16) __half g_wqh[QKV_E * DD];
__device__ __align__(16) __half g_woh[DD * DD];
__device__ __align__(16) __half g_ohi[MROWS * DD];
__device__ __align__(16) __half g_olo[MROWS * DD];
#define QKVN (BB * HH * SS * HDIM)
__device__ __align__(16) __half g_qh[QKVN];
__device__ __align__(16) __half g_ql[QKVN];
__device__ __align__(16) __half g_kh[QKVN];
__device__ __align__(16) __half g_vh[QKVN];

__device__ __forceinline__ unsigned smem_u32(const void* p) {
    unsigned a;
    asm("{ .reg .u64 t; cvta.to.shared.u64 t, %1; cvt.u32.u64 %0, t; }"
        : "=r"(a) : "l"(p));
    return a;
}

// ---------------------------------------------------------------------------
// Fused splits: x -> fp16 hi+lo ; w_qkv -> fp16 hi ; w_out -> fp16 hi
// ---------------------------------------------------------------------------
#define N4X (MROWS * DD / 4)      // 1048576
#define N4Q (QKV_E * DD / 4)      // 786432
#define N4W (DD * DD / 4)         // 262144
#define N4TOT (N4X + N4Q + N4W)   // 2097152

__global__ __launch_bounds__(256) void split_all(
    const float* __restrict__ x, const float* __restrict__ wq,
    const float* __restrict__ wo,
    __half* __restrict__ xhi, __half* __restrict__ xlo,
    __half* __restrict__ wqh, __half* __restrict__ woh)
{
    int i = blockIdx.x * blockDim.x + threadIdx.x;
    if (i >= N4TOT) return;
    if (i < N4X) {
        float4 v = *(const float4*)(x + (size_t)i * 4);
        __half h0 = __float2half_rn(v.x);
        __half h1 = __float2half_rn(v.y);
        __half h2 = __float2half_rn(v.z);
        __half h3 = __float2half_rn(v.w);
        __half2 H0; H0.x = h0; H0.y = h1;
        __half2 H1; H1.x = h2; H1.y = h3;
        ((__half2*)xhi)[i * 2 + 0] = H0;
        ((__half2*)xhi)[i * 2 + 1] = H1;
        __half2 L0, L1;
        L0.x = __float2half_rn(v.x - __half2float(h0));
        L0.y = __float2half_rn(v.y - __half2float(h1));
        L1.x = __float2half_rn(v.z - __half2float(h2));
        L1.y = __float2half_rn(v.w - __half2float(h3));
        ((__half2*)xlo)[i * 2 + 0] = L0;
        ((__half2*)xlo)[i * 2 + 1] = L1;
    } else {
        const float* src;
        __half* dst;
        int j;
        if (i < N4X + N4Q) { j = i - N4X; src = wq; dst = wqh; }
        else               { j = i - N4X - N4Q; src = wo; dst = woh; }
        float4 v = *(const float4*)(src + (size_t)j * 4);
        __half2 H0, H1;
        H0.x = __float2half_rn(v.x); H0.y = __float2half_rn(v.y);
        H1.x = __float2half_rn(v.z); H1.y = __float2half_rn(v.w);
        ((__half2*)dst)[j * 2 + 0] = H0;
        ((__half2*)dst)[j * 2 + 1] = H1;
    }
}

// ---------------------------------------------------------------------------
// MMA primitives
// ---------------------------------------------------------------------------
__device__ __forceinline__ void ldsm4(unsigned addr, unsigned& r0, unsigned& r1,
                                      unsigned& r2, unsigned& r3) {
    asm volatile("ldmatrix.sync.aligned.m8n8.x4.shared.b16 {%0,%1,%2,%3}, [%4];"
                 : "=r"(r0), "=r"(r1), "=r"(r2), "=r"(r3) : "r"(addr));
}
__device__ __forceinline__ void ldsm4t(unsigned addr, unsigned& r0, unsigned& r1,
                                       unsigned& r2, unsigned& r3) {
    asm volatile("ldmatrix.sync.aligned.m8n8.x4.trans.shared.b16 {%0,%1,%2,%3}, [%4];"
                 : "=r"(r0), "=r"(r1), "=r"(r2), "=r"(r3) : "r"(addr));
}
__device__ __forceinline__ void mma_fp(float* d, const unsigned* a,
                                       unsigned b0, unsigned b1) {
    asm volatile(
        "mma.sync.aligned.m16n8k16.row.col.f32.f16.f16.f32 "
        "{%0,%1,%2,%3}, {%4,%5,%6,%7}, {%8,%9}, {%0,%1,%2,%3};"
        : "+f"(d[0]), "+f"(d[1]), "+f"(d[2]), "+f"(d[3])
        : "r"(a[0]), "r"(a[1]), "r"(a[2]), "r"(a[3]), "r"(b0), "r"(b1));
}

// ---------------------------------------------------------------------------
// 2-pass exact-A x fp16(B) NT GEMM: C = (Ahi+Alo) @ Bhi^T (+bias).
// 128x128 block, KC=64, 256 thr, 2-stage cp.async, 2 CTAs/SM,
// single __syncthreads per K-chunk.
// MODE 0: fp32 C.  MODE 1: QKV epilogue (q scaled by QSC).
// ---------------------------------------------------------------------------
#define KC 64
#define STAGE_BYTES 49152          // Ahi 16K + Alo 16K + Bhi 16K
#define GM_SMEM (2 * STAGE_BYTES)  // 96KB -> 2 CTAs/SM

template <int MODE>
__global__ __launch_bounds__(256, 2) void gemm2(
    const __half* __restrict__ Ahi, const __half* __restrict__ Alo,
    const __half* __restrict__ Bhi,
    const float* __restrict__ bias, float* __restrict__ C,
    __half* __restrict__ qh, __half* __restrict__ ql,
    __half* __restrict__ kh, __half* __restrict__ vh,
    int M, int N, int K)
{
    extern __shared__ __align__(1024) char sm[];
    const unsigned sb = smem_u32(sm);
    const int tid  = threadIdx.x;
    const int lane = tid & 31;
    const int wid  = tid >> 5;
    const int wm   = wid >> 2;
    const int wn   = wid & 3;
    const int m0   = blockIdx.y * 128;
    const int n0   = blockIdx.x * 128;

    const __half* src0 = Ahi + (size_t)m0 * K;
    const __half* src1 = Alo + (size_t)m0 * K;
    const __half* src2 = Bhi + (size_t)n0 * K;

    const int lr0  = tid >> 3;
    const int lc16 = tid & 7;

    float acc[4][4][4];
#pragma unroll
    for (int i = 0; i < 4; i++)
#pragma unroll
        for (int j = 0; j < 4; j++)
#pragma unroll
            for (int q = 0; q < 4; q++) acc[i][j][q] = 0.f;

    const int nch = K / KC;

    auto issue = [&](int cc, int stg) {
        const int k0 = cc * KC;
        const unsigned sbase = sb + stg * STAGE_BYTES;
        const __half* srcs[3] = {src0, src1, src2};
#pragma unroll
        for (int op = 0; op < 3; op++) {
            const __half* s = srcs[op];
            const unsigned dst = sbase + op * 16384;
#pragma unroll
            for (int it = 0; it < 4; it++) {
                int r = lr0 + it * 32;
                unsigned saddr = dst + r * 128 + ((lc16 * 16) ^ ((r & 7) << 4));
                const void* g = s + (size_t)r * K + k0 + lc16 * 8;
                asm volatile("cp.async.cg.shared.global [%0], [%1], 16;"
                             :: "r"(saddr), "l"(g));
            }
        }
        asm volatile("cp.async.commit_group;" ::: "memory");
    };

    issue(0, 0);

    const int arow = (lane & 15);
    const unsigned acb0 = (lane >> 4) * 16;
    const int bnr  = (lane & 7) + ((lane >> 4) << 3);
    const unsigned bcb0 = ((lane >> 3) & 1) * 16;

    for (int cc = 0; cc < nch; cc++) {
        // stage cc is the only pending group
        asm volatile("cp.async.wait_group 0;" ::: "memory");
        __syncthreads();   // stage cc visible to all; all done reading stage cc-1
        if (cc + 1 < nch) issue(cc + 1, (cc + 1) & 1);

        const unsigned sbase = sb + (cc & 1) * STAGE_BYTES;
        const unsigned Ah = sbase, Al = sbase + 16384, Bb = sbase + 32768;

#pragma unroll
        for (int k16 = 0; k16 < 4; k16++) {
            unsigned ah[4][4], al[4][4];
#pragma unroll
            for (int mt = 0; mt < 4; mt++) {
                int r = wm * 64 + mt * 16 + arow;
                unsigned cb = k16 * 32 + acb0;
                unsigned off = r * 128 + (cb ^ ((r & 7) << 4));
                ldsm4(Ah + off, ah[mt][0], ah[mt][1], ah[mt][2], ah[mt][3]);
                ldsm4(Al + off, al[mt][0], al[mt][1], al[mt][2], al[mt][3]);
            }
            unsigned b[2][4];
#pragma unroll
            for (int bt = 0; bt < 2; bt++) {
                int n = wn * 32 + bt * 16 + bnr;
                unsigned cb = k16 * 32 + bcb0;
                unsigned addr = Bb + n * 128 + (cb ^ ((n & 7) << 4));
                ldsm4(addr, b[bt][0], b[bt][1], b[bt][2], b[bt][3]);
            }
#pragma unroll
            for (int mt = 0; mt < 4; mt++)
#pragma unroll
                for (int nt = 0; nt < 4; nt++)
                    mma_fp(acc[mt][nt], ah[mt],
                           b[nt >> 1][(nt & 1) * 2],
                           b[nt >> 1][(nt & 1) * 2 + 1]);
#pragma unroll
            for (int mt = 0; mt < 4; mt++)
#pragma unroll
                for (int nt = 0; nt < 4; nt++)
                    mma_fp(acc[mt][nt], al[mt],
                           b[nt >> 1][(nt & 1) * 2],
                           b[nt >> 1][(nt & 1) * 2 + 1]);
        }
    }

    // ---- epilogue ----
#pragma unroll
    for (int mt = 0; mt < 4; mt++) {
        int r0 = m0 + wm * 64 + mt * 16 + (lane >> 2);
#pragma unroll
        for (int nt = 0; nt < 4; nt++) {
            int c = n0 + wn * 32 + nt * 8 + (lane & 3) * 2;
            if (MODE == 0) {
                float2 bv = make_float2(0.f, 0.f);
                if (bias) bv = *(const float2*)(bias + c);
                *(float2*)(C + (size_t)r0 * N + c) =
                    make_float2(acc[mt][nt][0] + bv.x, acc[mt][nt][1] + bv.y);
                *(float2*)(C + (size_t)(r0 + 8) * N + c) =
                    make_float2(acc[mt][nt][2] + bv.x, acc[mt][nt][3] + bv.y);
            } else {
                int which = c >> 10;           // 0: v, 1: q, 2: k
                int rem   = c & 1023;
                int h     = rem >> 6;
                int d     = rem & 63;
#pragma unroll
                for (int half_ = 0; half_ < 2; half_++) {
                    int row = r0 + half_ * 8;
                    float v0 = acc[mt][nt][half_ * 2 + 0];
                    float v1 = acc[mt][nt][half_ * 2 + 1];
                    int b = row >> 11, s = row & 2047;
                    size_t idx = ((size_t)(b * HH + h) * SS + s) * HDIM + d;
                    if (which == 1) {
                        v0 *= QSC; v1 *= QSC;     // fold softmax scale + log2e
                        __half h0 = __float2half_rn(v0);
                        __half h1 = __float2half_rn(v1);
                        __half2 Hp; Hp.x = h0; Hp.y = h1;
                        __half2 Lp;
                        Lp.x = __float2half_rn(v0 - __half2float(h0));
                        Lp.y = __float2half_rn(v1 - __half2float(h1));
                        *(__half2*)(qh + idx) = Hp;
                        *(__half2*)(ql + idx) = Lp;
                    } else {
                        __half2 Hp;
                        Hp.x = __float2half_rn(v0);
                        Hp.y = __float2half_rn(v1);
                        __half* dst = (which == 0) ? vh : kh;
                        *(__half2*)(dst + idx) = Hp;
                    }
                }
            }
        }
    }
}

// ---------------------------------------------------------------------------
// Tensor-core flash attention, 2-pass, exp2-domain softmax.
// 128 q rows/block, 8 warps, BK=64, 2-stage cp.async KV, 2 CTAs/SM,
// single __syncthreads per KV tile.
// ---------------------------------------------------------------------------
#define FA_SMEM (32768 + 2 * 16384)   // Qhi/Qlo + 2 KV stages = 64KB

__global__ __launch_bounds__(256, 2) void flash_mma(
    const __half* __restrict__ Qhi, const __half* __restrict__ Qlo,
    const __half* __restrict__ Khi, const __half* __restrict__ Vhi,
    __half* __restrict__ Ohi, __half* __restrict__ Olo)
{
    extern __shared__ __align__(1024) char sm[];
    const unsigned sb = smem_u32(sm);
    const int tid  = threadIdx.x;
    const int lane = tid & 31;
    const int wid  = tid >> 5;
    const int q0   = blockIdx.x * 128;
    const int bh   = blockIdx.y;

    const size_t base = (size_t)bh * SS * HDIM;
    const __half* qhg = Qhi + base;
    const __half* qlg = Qlo + base;
    const __half* khg = Khi + base;
    const __half* vhg = Vhi + base;

    const unsigned sQh = sb, sQl = sb + 16384;
    const unsigned sStage = sb + 32768;

    // ---- Q tiles (128 x 64 fp16, hi+lo) ----
#pragma unroll
    for (int it = 0; it < 4; it++) {
        int idx = it * 256 + tid;
        int r   = idx >> 3;
        int c16 = idx & 7;
        unsigned off = r * 128 + ((c16 * 16) ^ ((r & 7) << 4));
        const void* gh = qhg + (size_t)(q0 + r) * HDIM + c16 * 8;
        const void* gl = qlg + (size_t)(q0 + r) * HDIM + c16 * 8;
        asm volatile("cp.async.cg.shared.global [%0], [%1], 16;"
                     :: "r"(sQh + off), "l"(gh));
        asm volatile("cp.async.cg.shared.global [%0], [%1], 16;"
                     :: "r"(sQl + off), "l"(gl));
    }
    asm volatile("cp.async.commit_group;" ::: "memory");

    auto issue_kv = [&](int i, int stg) {
        const int kv0 = i * 64;
        const unsigned s0 = sStage + stg * 16384;
        const __half* srcs[2] = {khg, vhg};
#pragma unroll
        for (int op = 0; op < 2; op++) {
            const unsigned dst = s0 + op * 8192;
#pragma unroll
            for (int it = 0; it < 2; it++) {
                int idx = it * 256 + tid;
                int r   = idx >> 3;
                int c16 = idx & 7;
                unsigned saddr = dst + r * 128 + ((c16 * 16) ^ ((r & 7) << 4));
                const void* g = srcs[op] + (size_t)(kv0 + r) * HDIM + c16 * 8;
                asm volatile("cp.async.cg.shared.global [%0], [%1], 16;"
                             :: "r"(saddr), "l"(g));
            }
        }
        asm volatile("cp.async.commit_group;" ::: "memory");
    };

    issue_kv(0, 0);
    asm volatile("cp.async.wait_group 0;" ::: "memory");   // Q + kv0 done
    __syncthreads();

    // ---- persistent Q a-frags ----
    unsigned qhf[4][4], qlf[4][4];
    {
        const int arow = wid * 16 + (lane & 15);
        const unsigned acb0 = (lane >> 4) * 16;
#pragma unroll
        for (int ks = 0; ks < 4; ks++) {
            unsigned cb = ks * 32 + acb0;
            unsigned off = arow * 128 + (cb ^ ((arow & 7) << 4));
            ldsm4(sQh + off, qhf[ks][0], qhf[ks][1], qhf[ks][2], qhf[ks][3]);
            ldsm4(sQl + off, qlf[ks][0], qlf[ks][1], qlf[ks][2], qlf[ks][3]);
        }
    }

    float o[8][4];
#pragma unroll
    for (int i = 0; i < 8; i++)
#pragma unroll
        for (int j = 0; j < 4; j++) o[i][j] = 0.f;
    float m0r = -1e30f, m1r = -1e30f, l0r = 0.f, l1r = 0.f;

    const int bnr  = (lane & 7) + ((lane >> 4) << 3);
    const unsigned bcb0 = ((lane >> 3) & 1) * 16;
    const int vrow0 = (lane & 7) + (((lane >> 3) & 1) << 3);
    const unsigned vcb = (lane >> 4) * 16;

    const int NIT = SS / 64;   // 32
    for (int cc = 0; cc < NIT; cc++) {
        asm volatile("cp.async.wait_group 0;" ::: "memory");   // stage cc ready
        __syncthreads();       // all warps done reading stage cc-1
        if (cc + 1 < NIT) issue_kv(cc + 1, (cc + 1) & 1);

        const unsigned st = sStage + (cc & 1) * 16384;
        const unsigned sKh = st, sVh = st + 8192;

        // ---- S = Q K^T (2-pass, exp2-domain logits) ----
        float s[8][4];
#pragma unroll
        for (int i = 0; i < 8; i++)
#pragma unroll
            for (int j = 0; j < 4; j++) s[i][j] = 0.f;

#pragma unroll
        for (int ks = 0; ks < 4; ks++) {
#pragma unroll
            for (int g = 0; g < 4; g++) {
                int r = g * 16 + bnr;
                unsigned cb = ks * 32 + bcb0;
                unsigned off = r * 128 + (cb ^ ((r & 7) << 4));
                unsigned h0, h1, h2, h3;
                ldsm4(sKh + off, h0, h1, h2, h3);
                mma_fp(s[2 * g],     qhf[ks], h0, h1);
                mma_fp(s[2 * g + 1], qhf[ks], h2, h3);
                mma_fp(s[2 * g],     qlf[ks], h0, h1);
                mma_fp(s[2 * g + 1], qlf[ks], h2, h3);
            }
        }

        // ---- online softmax in exp2 domain ----
        float mx0 = -1e30f, mx1 = -1e30f;
#pragma unroll
        for (int nt = 0; nt < 8; nt++) {
            mx0 = fmaxf(mx0, fmaxf(s[nt][0], s[nt][1]));
            mx1 = fmaxf(mx1, fmaxf(s[nt][2], s[nt][3]));
        }
        mx0 = fmaxf(mx0, __shfl_xor_sync(0xffffffffu, mx0, 1));
        mx0 = fmaxf(mx0, __shfl_xor_sync(0xffffffffu, mx0, 2));
        mx1 = fmaxf(mx1, __shfl_xor_sync(0xffffffffu, mx1, 1));
        mx1 = fmaxf(mx1, __shfl_xor_sync(0xffffffffu, mx1, 2));
        float mn0 = fmaxf(m0r, mx0), mn1 = fmaxf(m1r, mx1);
        float f0 = exp2f(m0r - mn0), f1 = exp2f(m1r - mn1);
        float sum0 = 0.f, sum1 = 0.f;
#pragma unroll
        for (int nt = 0; nt < 8; nt++) {
            s[nt][0] = exp2f(s[nt][0] - mn0);
            s[nt][1] = exp2f(s[nt][1] - mn0);
            s[nt][2] = exp2f(s[nt][2] - mn1);
            s[nt][3] = exp2f(s[nt][3] - mn1);
            sum0 += s[nt][0] + s[nt][1];
            sum1 += s[nt][2] + s[nt][3];
        }
        sum0 += __shfl_xor_sync(0xffffffffu, sum0, 1);
        sum0 += __shfl_xor_sync(0xffffffffu, sum0, 2);
        sum1 += __shfl_xor_sync(0xffffffffu, sum1, 1);
        sum1 += __shfl_xor_sync(0xffffffffu, sum1, 2);
        l0r = l0r * f0 + sum0;
        l1r = l1r * f1 + sum1;
        m0r = mn0; m1r = mn1;
#pragma unroll
        for (int nd = 0; nd < 8; nd++) {
            o[nd][0] *= f0; o[nd][1] *= f0;
            o[nd][2] *= f1; o[nd][3] *= f1;
        }

        // ---- O += P V (2-pass) ----
#pragma unroll
        for (int kk = 0; kk < 4; kk++) {
            float2 p00 = make_float2(s[2 * kk][0], s[2 * kk][1]);
            float2 p01 = make_float2(s[2 * kk][2], s[2 * kk][3]);
            float2 p10 = make_float2(s[2 * kk + 1][0], s[2 * kk + 1][1]);
            float2 p11 = make_float2(s[2 * kk + 1][2], s[2 * kk + 1][3]);
            __half2 H0 = __float22half2_rn(p00);
            __half2 H1 = __float22half2_rn(p01);
            __half2 H2 = __float22half2_rn(p10);
            __half2 H3 = __float22half2_rn(p11);
            float2 r0 = __half22float2(H0), r1 = __half22float2(H1);
            float2 r2 = __half22float2(H2), r3 = __half22float2(H3);
            __half2 L0 = __float22half2_rn(make_float2(p00.x - r0.x, p00.y - r0.y));
            __half2 L1 = __float22half2_rn(make_float2(p01.x - r1.x, p01.y - r1.y));
            __half2 L2 = __float22half2_rn(make_float2(p10.x - r2.x, p10.y - r2.y));
            __half2 L3 = __float22half2_rn(make_float2(p11.x - r3.x, p11.y - r3.y));
            unsigned pah[4] = {*(unsigned*)&H0, *(unsigned*)&H1,
                               *(unsigned*)&H2, *(unsigned*)&H3};
            unsigned pal[4] = {*(unsigned*)&L0, *(unsigned*)&L1,
                               *(unsigned*)&L2, *(unsigned*)&L3};

#pragma unroll
            for (int np = 0; np < 4; np++) {
                int r = kk * 16 + vrow0;
                unsigned cb = (np * 2) * 16 + vcb;
                unsigned off = r * 128 + (cb ^ ((r & 7) << 4));
                unsigned v0, v1, v2, v3;
                ldsm4t(sVh + off, v0, v1, v2, v3);
                mma_fp(o[2 * np],     pah, v0, v1);
                mma_fp(o[2 * np + 1], pah, v2, v3);
                mma_fp(o[2 * np],     pal, v0, v1);
                mma_fp(o[2 * np + 1], pal, v2, v3);
            }
        }
    }

    // ---- epilogue: normalize + write fp16 hi/lo [4096][1024] ----
    const float inv0 = 1.f / l0r, inv1 = 1.f / l1r;
    const int b = bh >> 4, h = bh & 15;
    const int row0 = q0 + wid * 16 + (lane >> 2);
    const int grow0 = b * SS + row0;
    const int col0 = h * HDIM + (lane & 3) * 2;
#pragma unroll
    for (int nd = 0; nd < 8; nd++) {
        int c = col0 + nd * 8;
#pragma unroll
        for (int half_ = 0; half_ < 2; half_++) {
            float v0 = o[nd][half_ * 2 + 0] * (half_ ? inv1 : inv0);
            float v1 = o[nd][half_ * 2 + 1] * (half_ ? inv1 : inv0);
            size_t idx = (size_t)(grow0 + half_ * 8) * DD + c;
            __half h0 = __float2half_rn(v0);
            __half h1 = __float2half_rn(v1);
            __half2 Hp; Hp.x = h0; Hp.y = h1;
            __half2 Lp;
            Lp.x = __float2half_rn(v0 - __half2float(h0));
            Lp.y = __float2half_rn(v1 - __half2float(h1));
            *(__half2*)(Ohi + idx) = Hp;
            *(__half2*)(Olo + idx) = Lp;
        }
    }
}

// ---------------------------------------------------------------------------
extern "C" void kernel_launch(void* const* d_in, const int* in_sizes, int n_in,
                              void* d_out, int out_size)
{
    const float* x     = (const float*)d_in[0];
    const float* w_qkv = (const float*)d_in[1];
    const float* w_out = (const float*)d_in[2];
    const float* b_out = (const float*)d_in[3];
    float* out = (float*)d_out;

    void *xhi_p, *xlo_p, *wqh_p, *woh_p, *ohi_p, *olo_p;
    void *qh_p, *ql_p, *kh_p, *vh_p;
    cudaGetSymbolAddress(&xhi_p, g_xhi);
    cudaGetSymbolAddress(&xlo_p, g_xlo);
    cudaGetSymbolAddress(&wqh_p, g_wqh);
    cudaGetSymbolAddress(&woh_p, g_woh);
    cudaGetSymbolAddress(&ohi_p, g_ohi);
    cudaGetSymbolAddress(&olo_p, g_olo);
    cudaGetSymbolAddress(&qh_p, g_qh);
    cudaGetSymbolAddress(&ql_p, g_ql);
    cudaGetSymbolAddress(&kh_p, g_kh);
    cudaGetSymbolAddress(&vh_p, g_vh);

    cudaFuncSetAttribute(gemm2<0>,
                         cudaFuncAttributeMaxDynamicSharedMemorySize, GM_SMEM);
    cudaFuncSetAttribute(gemm2<1>,
                         cudaFuncAttributeMaxDynamicSharedMemorySize, GM_SMEM);
    cudaFuncSetAttribute(flash_mma,
                         cudaFuncAttributeMaxDynamicSharedMemorySize, FA_SMEM);

    // 0) fused splits
    split_all<<<(N4TOT + 255) / 256, 256>>>(
        x, w_qkv, w_out,
        (__half*)xhi_p, (__half*)xlo_p, (__half*)wqh_p, (__half*)woh_p);

    // 1) QKV projection -> q hi/lo (scaled by SCALE*log2e), k hi, v hi
    dim3 g1(QKV_E / 128, MROWS / 128);
    gemm2<1><<<g1, 256, GM_SMEM>>>(
        (const __half*)xhi_p, (const __half*)xlo_p, (const __half*)wqh_p,
        nullptr, nullptr,
        (__half*)qh_p, (__half*)ql_p, (__half*)kh_p, (__half*)vh_p,
        MROWS, QKV_E, DD);

    // 2) flash attention -> o fp16 hi/lo
    dim3 g2(SS / 128, BB * HH);
    flash_mma<<<g2, 256, FA_SMEM>>>(
        (const __half*)qh_p, (const __half*)ql_p,
        (const __half*)kh_p, (const __half*)vh_p,
        (__half*)ohi_p, (__half*)olo_p);

    // 3) output projection with bias -> fp32 out
    dim3 g3(DD / 128, MROWS / 128);
    gemm2<0><<<g3, 256, GM_SMEM>>>(
        (const __half*)ohi_p, (const __half*)olo_p, (const __half*)woh_p,
        b_out, out,
        nullptr, nullptr, nullptr, nullptr,
        MROWS, DD, DD);
}